// round 8
// baseline (speedup 1.0000x reference)
#include <cuda_runtime.h>
#include <cuda_fp16.h>

// VectorQuantizer: one bf16 mma.sync pass caching dots as fp16 in smem,
// smem-scan collect pass, exact fp32 re-score of queued candidates.
// inputs [32,64,64,64] f32 NCHW, weight [512,64] f32.
// out[0..N*D) = fl(x + fl(q-x)) NCHW; out[N*D..) = 1.25*mean((q-x)^2).

#define KCODES  512
#define DDIM    64
#define HWSZ    4096
#define NTOT    131072
#define TILE_M  128
#define NTILES  (NTOT / TILE_M)   // 1024
#define NTHREADS 512
#define QCAP    2048

typedef unsigned int u32;
typedef unsigned long long u64;

__device__ float g_partials[NTILES];

// ---- smem layout (bytes) ----
#define BSTRIDE   520                    // u32 per c2-row of codebook (conflict-free)
#define OFF_B     0                      // bf16x2 codebook [32][520] = 66560
#define OFF_S     66560                  // fp16 dots [128][522] = 133632  (A32 aliased here)
#define SROW      1044                   // bytes per dot row (522 halves; 261 words, gcd(261,32)=1)
#define OFF_A     OFF_S                  // fp32 x-tile [128][65] = 33280 (transient)
#define ASTRIDE   65
#define OFF_SWN   (OFF_S + 133632)       // 512 f32 = 2048
#define OFF_SX    (OFF_SWN + 2048)       // 128 f32 = 512
#define OFF_KEY   (OFF_SX + 512)         // 128 u64 = 1024
#define OFF_BMH   (OFF_KEY + 1024)       // 128*4 f32 = 2048
#define OFF_QCNT  (OFF_BMH + 2048)       // 16
#define OFF_OVF   (OFF_QCNT + 16)        // 128
#define OFF_QUE   (OFF_OVF + 128)        // QCAP*4 = 8192
#define SMEM_TOTAL (OFF_QUE + QCAP * 4)  // 214096

// ---- scalar helpers ----
__device__ __forceinline__ u32 bf16x2_pack(float lo, float hi) {
    u32 r; asm("cvt.rn.bf16x2.f32 %0, %1, %2;" : "=r"(r) : "f"(hi), "f"(lo)); return r;
}
__device__ __forceinline__ u64 ffma2(u64 a, u64 b, u64 c) {
    u64 d; asm("fma.rn.f32x2 %0, %1, %2, %3;" : "=l"(d) : "l"(a), "l"(b), "l"(c)); return d;
}
__device__ __forceinline__ u64 fadd2(u64 a, u64 b) {
    u64 d; asm("add.rn.f32x2 %0, %1, %2;" : "=l"(d) : "l"(a), "l"(b)); return d;
}
__device__ __forceinline__ u64 pack2(float lo, float hi) {
    u64 d; asm("mov.b64 %0, {%1, %2};" : "=l"(d) : "f"(lo), "f"(hi)); return d;
}
__device__ __forceinline__ void unpack2(u64 v, float& lo, float& hi) {
    asm("mov.b64 {%0, %1}, %2;" : "=f"(lo), "=f"(hi) : "l"(v));
}

#define MMAB(c, a, b0, b1)                                                      \
    asm volatile("mma.sync.aligned.m16n8k16.row.col.f32.bf16.bf16.f32 "         \
                 "{%0,%1,%2,%3}, {%4,%5,%6,%7}, {%8,%9}, {%0,%1,%2,%3};"        \
                 : "+f"((c)[0]), "+f"((c)[1]), "+f"((c)[2]), "+f"((c)[3])       \
                 : "r"((a)[0]), "r"((a)[1]), "r"((a)[2]), "r"((a)[3]),          \
                   "r"(b0), "r"(b1))

// exact fp32 score, bit-identical to the round-2 passing pipeline.
// x read with stride (gmem NCHW); values identical to smem copy.
__device__ __forceinline__ float exact_d_g(const float* __restrict__ xg,
                                           const float* __restrict__ wrow,
                                           float sx, float swn_k) {
    u64 a0 = 0ull, a1 = 0ull, a2 = 0ull, a3 = 0ull;
    #pragma unroll
    for (int j = 0; j < DDIM / 2; j += 4) {
        u64 x0 = pack2(xg[(size_t)(2*(j+0))*HWSZ],   xg[(size_t)(2*(j+0)+1)*HWSZ]);
        u64 x1 = pack2(xg[(size_t)(2*(j+1))*HWSZ],   xg[(size_t)(2*(j+1)+1)*HWSZ]);
        u64 x2 = pack2(xg[(size_t)(2*(j+2))*HWSZ],   xg[(size_t)(2*(j+2)+1)*HWSZ]);
        u64 x3 = pack2(xg[(size_t)(2*(j+3))*HWSZ],   xg[(size_t)(2*(j+3)+1)*HWSZ]);
        u64 w0 = pack2(wrow[2*(j+0)], wrow[2*(j+0)+1]);
        u64 w1 = pack2(wrow[2*(j+1)], wrow[2*(j+1)+1]);
        u64 w2 = pack2(wrow[2*(j+2)], wrow[2*(j+2)+1]);
        u64 w3 = pack2(wrow[2*(j+3)], wrow[2*(j+3)+1]);
        a0 = ffma2(x0, w0, a0);
        a1 = ffma2(x1, w1, a1);
        a2 = ffma2(x2, w2, a2);
        a3 = ffma2(x3, w3, a3);
    }
    a0 = fadd2(a0, a1);
    a2 = fadd2(a2, a3);
    a0 = fadd2(a0, a2);
    float lo, hi;
    unpack2(a0, lo, hi);
    float dot = __fadd_rn(lo, hi);
    float t = __fadd_rn(sx, swn_k);
    return __fsub_rn(t, __fmul_rn(2.0f, dot));
}

extern __shared__ char smem[];

__global__ void __launch_bounds__(NTHREADS, 1)
vq_mma_kernel(const float* __restrict__ input,
              const float* __restrict__ weight,
              float* __restrict__ out)
{
    u32*   Bp    = (u32*)(smem + OFF_B);
    float* A32   = (float*)(smem + OFF_A);
    float* SWN   = (float*)(smem + OFF_SWN);
    float* SX    = (float*)(smem + OFF_SX);
    u64*   KEY   = (u64*)(smem + OFF_KEY);
    float* BMH   = (float*)(smem + OFF_BMH);
    u32*   QCNT  = (u32*)(smem + OFF_QCNT);
    unsigned char* SOVF = (unsigned char*)(smem + OFF_OVF);
    u32*   QUE   = (u32*)(smem + OFF_QUE);

    const int tid = threadIdx.x;
    const int b   = blockIdx.x >> 5;            // 32 tiles per batch image
    const int hw0 = (blockIdx.x & 31) * TILE_M;
    const float* xbase = input + (size_t)b * DDIM * HWSZ + hw0;

    if (tid < TILE_M) { KEY[tid] = ~0ull; SOVF[tid] = 0; }
    if (tid == 0) *QCNT = 0;

    // ---- stage A (fp32, transient, aliased under dot cache) + exact sx ----
    if (tid < TILE_M) {
        const float* xg = xbase + tid;
        float* arow = A32 + tid * ASTRIDE;
        float sx = 0.f;
        #pragma unroll
        for (int c = 0; c < DDIM; c++) {
            float v = xg[(size_t)c * HWSZ];
            arow[c] = v;
            sx = __fadd_rn(sx, __fmul_rn(v, v));
        }
        SX[tid] = sx;
    }

    // ---- stage B (bf16 pairs, [c2][n]) + exact sequential norms (n = tid) ----
    {
        const int n = tid;
        const float4* wr = (const float4*)(weight + (size_t)n * DDIM);
        float s = 0.f;
        #pragma unroll
        for (int c4 = 0; c4 < DDIM / 4; c4++) {
            float4 wv = wr[c4];
            s = __fadd_rn(s, __fmul_rn(wv.x, wv.x));
            s = __fadd_rn(s, __fmul_rn(wv.y, wv.y));
            s = __fadd_rn(s, __fmul_rn(wv.z, wv.z));
            s = __fadd_rn(s, __fmul_rn(wv.w, wv.w));
            Bp[(c4 * 2 + 0) * BSTRIDE + n] = bf16x2_pack(wv.x, wv.y);
            Bp[(c4 * 2 + 1) * BSTRIDE + n] = bf16x2_pack(wv.z, wv.w);
        }
        SWN[n] = s;
    }
    __syncthreads();

    // ---- warp roles: 4 row-groups (32 rows) x 4 code-quarters (128 codes) ----
    const int lane  = tid & 31;
    const int g     = lane >> 2;
    const int tq    = lane & 3;
    const int w     = tid >> 5;
    const int rbase = (w >> 2) * 32;
    const int q     = w & 3;
    const int nb0   = q * 128;

    // ---- A fragments (bf16) from transient A32 ----
    u32 afr[2][4][4];
    #pragma unroll
    for (int mt = 0; mt < 2; mt++) {
        const float* r0 = A32 + (rbase + mt * 16 + g) * ASTRIDE;
        const float* r1 = r0 + 8 * ASTRIDE;
        #pragma unroll
        for (int ks = 0; ks < 4; ks++) {
            const int k0 = ks * 16 + 2 * tq;
            afr[mt][ks][0] = bf16x2_pack(r0[k0],     r0[k0 + 1]);
            afr[mt][ks][1] = bf16x2_pack(r1[k0],     r1[k0 + 1]);
            afr[mt][ks][2] = bf16x2_pack(r0[k0 + 8], r0[k0 + 9]);
            afr[mt][ks][3] = bf16x2_pack(r1[k0 + 8], r1[k0 + 9]);
        }
    }
    __syncthreads();   // all fragments built before dot cache overwrites A32

    // ================= MMA pass: min + fp16 dot cache =================
    float bmin[4] = {3.4e38f, 3.4e38f, 3.4e38f, 3.4e38f};

    #pragma unroll 1
    for (int n2 = 0; n2 < 8; n2++) {
        const int nb = nb0 + n2 * 16;
        float acc[2][2][4];
        #pragma unroll
        for (int i = 0; i < 2; i++)
            #pragma unroll
            for (int j = 0; j < 2; j++)
                #pragma unroll
                for (int e = 0; e < 4; e++) acc[i][j][e] = 0.f;

        #pragma unroll
        for (int ks = 0; ks < 4; ks++) {
            const u32* p0 = Bp + (ks * 8 + tq) * BSTRIDE + nb + g;
            const u32* p1 = p0 + 4 * BSTRIDE;
            u32 b0a = p0[0], b0b = p0[8];
            u32 b1a = p1[0], b1b = p1[8];
            MMAB(acc[0][0], afr[0][ks], b0a, b1a);
            MMAB(acc[0][1], afr[0][ks], b0b, b1b);
            MMAB(acc[1][0], afr[1][ks], b0a, b1a);
            MMAB(acc[1][1], afr[1][ks], b0b, b1b);
        }

        float swnc[2][2];
        swnc[0][0] = SWN[nb + tq * 2];
        swnc[0][1] = SWN[nb + tq * 2 + 1];
        swnc[1][0] = SWN[nb + 8 + tq * 2];
        swnc[1][1] = SWN[nb + 8 + tq * 2 + 1];

        #pragma unroll
        for (int mt = 0; mt < 2; mt++)
        #pragma unroll
        for (int nn = 0; nn < 2; nn++)
        #pragma unroll
        for (int ep = 0; ep < 2; ep++) {
            const int s   = mt * 2 + ep;
            const int row = rbase + mt * 16 + ep * 8 + g;
            const int col = nb + nn * 8 + tq * 2;
            float d0 = acc[mt][nn][ep * 2 + 0];
            float d1 = acc[mt][nn][ep * 2 + 1];
            // cache dots as fp16 pair
            *(__half2*)(smem + OFF_S + row * SROW + col * 2) = __floats2half2_rn(d0, d1);
            // track min of approx score
            float s0 = fmaf(-2.f, d0, swnc[nn][0]);
            float s1 = fmaf(-2.f, d1, swnc[nn][1]);
            bmin[s] = fminf(bmin[s], fminf(s0, s1));
        }
    }

    // quad-merge mins; publish per (row, quarter)
    const unsigned FULL = 0xffffffffu;
    #pragma unroll
    for (int s = 0; s < 4; s++) {
        float bm = bmin[s];
        bm = fminf(bm, __shfl_xor_sync(FULL, bm, 1));
        bm = fminf(bm, __shfl_xor_sync(FULL, bm, 2));
        if (tq == 0) {
            int row = rbase + (s >> 1) * 16 + (s & 1) * 8 + g;
            BMH[row * 4 + q] = bm;
        }
    }
    __syncthreads();

    // ================= collect pass: smem dot scan =================
    {
        const int row  = tid & 127;
        const int part = tid >> 7;          // 0..3, 128 codes each
        const int ks0  = part * 128;

        float bm = fminf(fminf(BMH[row * 4 + 0], BMH[row * 4 + 1]),
                         fminf(BMH[row * 4 + 2], BMH[row * 4 + 3]));
        // margin: bf16 MMA err (<=2.44e-4*sqrt(sx)) x2 + fp16 dot quant (2*6e-5)
        float th = bm + fmaf(sqrtf(SX[row]), 5e-4f, 2e-4f);

        const __half2* drow = (const __half2*)(smem + OFF_S + row * SROW) + (ks0 >> 1);
        #pragma unroll 4
        for (int j = 0; j < 64; j++) {
            float2 dd = __half22float2(drow[j]);
            int k = ks0 + 2 * j;
            float s0 = fmaf(-2.f, dd.x, SWN[k]);
            float s1 = fmaf(-2.f, dd.y, SWN[k + 1]);
            if (s0 <= th) {
                u32 pos = atomicAdd(QCNT, 1u);
                if (pos < QCAP) QUE[pos] = ((u32)row << 16) | (u32)k;
                else SOVF[row] = 1;
            }
            if (s1 <= th) {
                u32 pos = atomicAdd(QCNT, 1u);
                if (pos < QCAP) QUE[pos] = ((u32)row << 16) | (u32)(k + 1);
                else SOVF[row] = 1;
            }
        }
    }
    __syncthreads();

    // ================= exact rescore of queue (cooperative) =================
    {
        int qn = *QCNT;
        if (qn > QCAP) qn = QCAP;
        for (int i = tid; i < qn; i += NTHREADS) {
            u32 e = QUE[i];
            int row = e >> 16;
            int k   = e & 0xffff;
            float d = exact_d_g(xbase + row, weight + (size_t)k * DDIM,
                                SX[row], SWN[k]);
            u64 key = ((u64)__float_as_uint(d) << 16) | (u64)k;
            atomicMin(&KEY[row], key);
        }
    }
    __syncthreads();

    // ================= epilogue: 4 threads per row (c split by 16) ==========
    {
        const int row = tid & 127;
        const int c0  = (tid >> 7) * 16;
        const float* xg = xbase + row;
        const float sxr = SX[row];

        int bidx;
        if (SOVF[row]) {   // overflow fallback (never expected): exact full scan
            float best = 3.4e38f; bidx = 0;
            for (int k = 0; k < KCODES; k++) {
                float d = exact_d_g(xg, weight + (size_t)k * DDIM, sxr, SWN[k]);
                if (d < best) { best = d; bidx = k; }
            }
        } else {
            bidx = (int)(KEY[row] & 0xffffull);
        }

        const float* qrow = weight + (size_t)bidx * DDIM;
        float* outp = out + (size_t)b * DDIM * HWSZ + hw0 + row;
        float lloss = 0.f;
        #pragma unroll
        for (int c = c0; c < c0 + 16; c++) {
            float x = xg[(size_t)c * HWSZ];
            float qv = qrow[c];
            float e = __fsub_rn(qv, x);
            outp[(size_t)c * HWSZ] = __fadd_rn(x, e);
            lloss = fmaf(e, e, lloss);
        }

        // deterministic loss reduction (reuse codebook region; B no longer needed)
        float* red = (float*)(smem + OFF_B);
        __syncthreads();
        red[tid] = lloss;
        __syncthreads();
        #pragma unroll
        for (int st = NTHREADS / 2; st > 0; st >>= 1) {
            if (tid < st) red[tid] += red[tid + st];
            __syncthreads();
        }
        if (tid == 0) g_partials[blockIdx.x] = red[0];
    }
}

__global__ void loss_kernel(float* __restrict__ out, int out_size)
{
    __shared__ float red[256];
    const int tid = threadIdx.x;
    float s = 0.f;
    for (int i = tid; i < NTILES; i += 256) s += g_partials[i];
    red[tid] = s;
    __syncthreads();
    #pragma unroll
    for (int st = 128; st > 0; st >>= 1) {
        if (tid < st) red[tid] += red[tid + st];
        __syncthreads();
    }
    if (tid == 0) {
        float loss = red[0] * 1.25f / (float)((long long)NTOT * DDIM);
        for (long long i = (long long)NTOT * DDIM; i < out_size; i++)
            out[i] = loss;
    }
}

extern "C" void kernel_launch(void* const* d_in, const int* in_sizes, int n_in,
                              void* d_out, int out_size)
{
    const float* input  = (const float*)d_in[0];
    const float* weight = (const float*)d_in[1];
    float* out = (float*)d_out;

    cudaFuncSetAttribute(vq_mma_kernel, cudaFuncAttributeMaxDynamicSharedMemorySize, SMEM_TOTAL);
    vq_mma_kernel<<<NTILES, NTHREADS, SMEM_TOTAL>>>(input, weight, out);
    loss_kernel<<<1, 256>>>(out, out_size);
}

// round 9
// speedup vs baseline: 1.2130x; 1.2130x over previous
#include <cuda_runtime.h>
#include <cuda_fp16.h>

// VectorQuantizer, persistent kernel: codebook staged once per CTA; loop over
// 128-row tiles; one bf16 mma.sync pass caching dots as fp16 in smem;
// smem-scan collect; exact fp32 re-score of queued candidates.
// inputs [32,64,64,64] f32 NCHW, weight [512,64] f32.
// out[0..N*D) = fl(x + fl(q-x)) NCHW; out[N*D..) = 1.25*mean((q-x)^2).

#define KCODES  512
#define DDIM    64
#define HWSZ    4096
#define NTOT    131072
#define TILE_M  128
#define NTILES  (NTOT / TILE_M)   // 1024
#define GRIDN   148
#define NTHREADS 512
#define QCAP    2048

typedef unsigned int u32;
typedef unsigned long long u64;

__device__ float g_partials[GRIDN];

// ---- smem layout (bytes) ----
#define BSTRIDE   520                    // u32 per c2-row of codebook (conflict-free)
#define OFF_B     0                      // bf16x2 codebook [32][520] = 66560 (persistent)
#define OFF_S     66560                  // fp16 dots [128][522] = 133632  (A32 aliased)
#define SROW      1044                   // bytes per dot row (261 words, gcd(261,32)=1)
#define OFF_A     OFF_S                  // fp32 x-tile [128][65] = 33280 (transient)
#define ASTRIDE   65
#define OFF_SWN   (OFF_S + 133632)       // 512 f32 = 2048 (persistent)
#define OFF_SX    (OFF_SWN + 2048)       // 128 f32 = 512
#define OFF_KEY   (OFF_SX + 512)         // 128 u64 = 1024
#define OFF_BMH   (OFF_KEY + 1024)       // 128*4 f32 = 2048
#define OFF_QCNT  (OFF_BMH + 2048)       // 16
#define OFF_OVF   (OFF_QCNT + 16)        // 128
#define OFF_QUE   (OFF_OVF + 128)        // QCAP*4 = 8192
#define SMEM_TOTAL (OFF_QUE + QCAP * 4)  // 214096

// ---- scalar helpers ----
__device__ __forceinline__ u32 bf16x2_pack(float lo, float hi) {
    u32 r; asm("cvt.rn.bf16x2.f32 %0, %1, %2;" : "=r"(r) : "f"(hi), "f"(lo)); return r;
}
__device__ __forceinline__ u64 ffma2(u64 a, u64 b, u64 c) {
    u64 d; asm("fma.rn.f32x2 %0, %1, %2, %3;" : "=l"(d) : "l"(a), "l"(b), "l"(c)); return d;
}
__device__ __forceinline__ u64 fadd2(u64 a, u64 b) {
    u64 d; asm("add.rn.f32x2 %0, %1, %2;" : "=l"(d) : "l"(a), "l"(b)); return d;
}
__device__ __forceinline__ u64 pack2(float lo, float hi) {
    u64 d; asm("mov.b64 %0, {%1, %2};" : "=l"(d) : "f"(lo), "f"(hi)); return d;
}
__device__ __forceinline__ void unpack2(u64 v, float& lo, float& hi) {
    asm("mov.b64 {%0, %1}, %2;" : "=f"(lo), "=f"(hi) : "l"(v));
}

#define MMAB(c, a, b0, b1)                                                      \
    asm volatile("mma.sync.aligned.m16n8k16.row.col.f32.bf16.bf16.f32 "         \
                 "{%0,%1,%2,%3}, {%4,%5,%6,%7}, {%8,%9}, {%0,%1,%2,%3};"        \
                 : "+f"((c)[0]), "+f"((c)[1]), "+f"((c)[2]), "+f"((c)[3])       \
                 : "r"((a)[0]), "r"((a)[1]), "r"((a)[2]), "r"((a)[3]),          \
                   "r"(b0), "r"(b1))

// exact fp32 score, bit-identical to the round-2 passing pipeline;
// x read strided from gmem (values identical to the staged copy).
__device__ __forceinline__ float exact_d_g(const float* __restrict__ xg,
                                           const float* __restrict__ wrow,
                                           float sx, float swn_k) {
    u64 a0 = 0ull, a1 = 0ull, a2 = 0ull, a3 = 0ull;
    #pragma unroll
    for (int j = 0; j < DDIM / 2; j += 4) {
        u64 x0 = pack2(xg[(size_t)(2*(j+0))*HWSZ],   xg[(size_t)(2*(j+0)+1)*HWSZ]);
        u64 x1 = pack2(xg[(size_t)(2*(j+1))*HWSZ],   xg[(size_t)(2*(j+1)+1)*HWSZ]);
        u64 x2 = pack2(xg[(size_t)(2*(j+2))*HWSZ],   xg[(size_t)(2*(j+2)+1)*HWSZ]);
        u64 x3 = pack2(xg[(size_t)(2*(j+3))*HWSZ],   xg[(size_t)(2*(j+3)+1)*HWSZ]);
        u64 w0 = pack2(wrow[2*(j+0)], wrow[2*(j+0)+1]);
        u64 w1 = pack2(wrow[2*(j+1)], wrow[2*(j+1)+1]);
        u64 w2 = pack2(wrow[2*(j+2)], wrow[2*(j+2)+1]);
        u64 w3 = pack2(wrow[2*(j+3)], wrow[2*(j+3)+1]);
        a0 = ffma2(x0, w0, a0);
        a1 = ffma2(x1, w1, a1);
        a2 = ffma2(x2, w2, a2);
        a3 = ffma2(x3, w3, a3);
    }
    a0 = fadd2(a0, a1);
    a2 = fadd2(a2, a3);
    a0 = fadd2(a0, a2);
    float lo, hi;
    unpack2(a0, lo, hi);
    float dot = __fadd_rn(lo, hi);
    float t = __fadd_rn(sx, swn_k);
    return __fsub_rn(t, __fmul_rn(2.0f, dot));
}

extern __shared__ char smem[];

__global__ void __launch_bounds__(NTHREADS, 1)
vq_mma_kernel(const float* __restrict__ input,
              const float* __restrict__ weight,
              float* __restrict__ out)
{
    u32*   Bp    = (u32*)(smem + OFF_B);
    float* A32   = (float*)(smem + OFF_A);
    float* SWN   = (float*)(smem + OFF_SWN);
    float* SX    = (float*)(smem + OFF_SX);
    u64*   KEY   = (u64*)(smem + OFF_KEY);
    float* BMH   = (float*)(smem + OFF_BMH);
    u32*   QCNT  = (u32*)(smem + OFF_QCNT);
    unsigned char* SOVF = (unsigned char*)(smem + OFF_OVF);
    u32*   QUE   = (u32*)(smem + OFF_QUE);

    const int tid = threadIdx.x;

    // ---- stage B ONCE (bf16 pairs, [c2][n]) + exact sequential norms ----
    {
        const int n = tid;
        const float4* wr = (const float4*)(weight + (size_t)n * DDIM);
        float s = 0.f;
        #pragma unroll
        for (int c4 = 0; c4 < DDIM / 4; c4++) {
            float4 wv = wr[c4];
            s = __fadd_rn(s, __fmul_rn(wv.x, wv.x));
            s = __fadd_rn(s, __fmul_rn(wv.y, wv.y));
            s = __fadd_rn(s, __fmul_rn(wv.z, wv.z));
            s = __fadd_rn(s, __fmul_rn(wv.w, wv.w));
            Bp[(c4 * 2 + 0) * BSTRIDE + n] = bf16x2_pack(wv.x, wv.y);
            Bp[(c4 * 2 + 1) * BSTRIDE + n] = bf16x2_pack(wv.z, wv.w);
        }
        SWN[n] = s;
    }

    // warp roles (fixed): 4 row-groups (32 rows) x 4 code-quarters (128 codes)
    const int lane  = tid & 31;
    const int g     = lane >> 2;
    const int tq    = lane & 3;
    const int w     = tid >> 5;
    const int rbase = (w >> 2) * 32;
    const int q     = w & 3;
    const int nb0   = q * 128;
    const unsigned FULL = 0xffffffffu;

    float lloss_acc = 0.f;
    __syncthreads();

    // ================= persistent tile loop =================
    for (int t = blockIdx.x; t < NTILES; t += GRIDN) {
        const int b   = t >> 5;
        const int hw0 = (t & 31) * TILE_M;
        const float* xbase = input + (size_t)b * DDIM * HWSZ + hw0;

        if (tid < TILE_M) { KEY[tid] = ~0ull; SOVF[tid] = 0; }
        if (tid == 0) *QCNT = 0;

        // ---- stage A coalesced: thread -> (row = tid&127, c-part = tid>>7) ----
        {
            const int row = tid & 127;
            const int c0  = (tid >> 7) * 16;
            #pragma unroll
            for (int i = 0; i < 16; i++) {
                int c = c0 + i;
                A32[row * ASTRIDE + c] = xbase[row + (size_t)c * HWSZ];
            }
        }
        __syncthreads();

        // ---- exact sequential sx from staged A (threads 0..127) ----
        if (tid < TILE_M) {
            const float* arow = A32 + tid * ASTRIDE;
            float sx = 0.f;
            #pragma unroll
            for (int c = 0; c < DDIM; c++)
                sx = __fadd_rn(sx, __fmul_rn(arow[c], arow[c]));
            SX[tid] = sx;
        }

        // ---- A fragments (bf16) from transient A32 ----
        u32 afr[2][4][4];
        #pragma unroll
        for (int mt = 0; mt < 2; mt++) {
            const float* r0 = A32 + (rbase + mt * 16 + g) * ASTRIDE;
            const float* r1 = r0 + 8 * ASTRIDE;
            #pragma unroll
            for (int ks = 0; ks < 4; ks++) {
                const int k0 = ks * 16 + 2 * tq;
                afr[mt][ks][0] = bf16x2_pack(r0[k0],     r0[k0 + 1]);
                afr[mt][ks][1] = bf16x2_pack(r1[k0],     r1[k0 + 1]);
                afr[mt][ks][2] = bf16x2_pack(r0[k0 + 8], r0[k0 + 9]);
                afr[mt][ks][3] = bf16x2_pack(r1[k0 + 8], r1[k0 + 9]);
            }
        }
        __syncthreads();   // fragments + sx done before dot cache overwrites A32

        // ---- MMA pass: min + fp16 dot cache ----
        float bmin[4] = {3.4e38f, 3.4e38f, 3.4e38f, 3.4e38f};

        #pragma unroll 1
        for (int n2 = 0; n2 < 8; n2++) {
            const int nb = nb0 + n2 * 16;
            float acc[2][2][4];
            #pragma unroll
            for (int i = 0; i < 2; i++)
                #pragma unroll
                for (int j = 0; j < 2; j++)
                    #pragma unroll
                    for (int e = 0; e < 4; e++) acc[i][j][e] = 0.f;

            #pragma unroll
            for (int ks = 0; ks < 4; ks++) {
                const u32* p0 = Bp + (ks * 8 + tq) * BSTRIDE + nb + g;
                const u32* p1 = p0 + 4 * BSTRIDE;
                u32 b0a = p0[0], b0b = p0[8];
                u32 b1a = p1[0], b1b = p1[8];
                MMAB(acc[0][0], afr[0][ks], b0a, b1a);
                MMAB(acc[0][1], afr[0][ks], b0b, b1b);
                MMAB(acc[1][0], afr[1][ks], b0a, b1a);
                MMAB(acc[1][1], afr[1][ks], b0b, b1b);
            }

            float swnc[2][2];
            swnc[0][0] = SWN[nb + tq * 2];
            swnc[0][1] = SWN[nb + tq * 2 + 1];
            swnc[1][0] = SWN[nb + 8 + tq * 2];
            swnc[1][1] = SWN[nb + 8 + tq * 2 + 1];

            #pragma unroll
            for (int mt = 0; mt < 2; mt++)
            #pragma unroll
            for (int nn = 0; nn < 2; nn++)
            #pragma unroll
            for (int ep = 0; ep < 2; ep++) {
                const int s   = mt * 2 + ep;
                const int row = rbase + mt * 16 + ep * 8 + g;
                const int col = nb + nn * 8 + tq * 2;
                float d0 = acc[mt][nn][ep * 2 + 0];
                float d1 = acc[mt][nn][ep * 2 + 1];
                *(__half2*)(smem + OFF_S + row * SROW + col * 2) = __floats2half2_rn(d0, d1);
                float s0 = fmaf(-2.f, d0, swnc[nn][0]);
                float s1 = fmaf(-2.f, d1, swnc[nn][1]);
                bmin[s] = fminf(bmin[s], fminf(s0, s1));
            }
        }

        // quad-merge mins; publish per (row, quarter)
        #pragma unroll
        for (int s = 0; s < 4; s++) {
            float bm = bmin[s];
            bm = fminf(bm, __shfl_xor_sync(FULL, bm, 1));
            bm = fminf(bm, __shfl_xor_sync(FULL, bm, 2));
            if (tq == 0) {
                int row = rbase + (s >> 1) * 16 + (s & 1) * 8 + g;
                BMH[row * 4 + q] = bm;
            }
        }
        __syncthreads();

        // ---- collect pass: smem dot scan ----
        {
            const int row  = tid & 127;
            const int part = tid >> 7;
            const int ks0  = part * 128;

            float bm = fminf(fminf(BMH[row * 4 + 0], BMH[row * 4 + 1]),
                             fminf(BMH[row * 4 + 2], BMH[row * 4 + 3]));
            // margin: bf16 MMA err x2 + fp16 dot quantization
            float th = bm + fmaf(sqrtf(SX[row]), 5e-4f, 2e-4f);

            const __half2* drow = (const __half2*)(smem + OFF_S + row * SROW) + (ks0 >> 1);
            #pragma unroll 4
            for (int j = 0; j < 64; j++) {
                float2 dd = __half22float2(drow[j]);
                int k = ks0 + 2 * j;
                float s0 = fmaf(-2.f, dd.x, SWN[k]);
                float s1 = fmaf(-2.f, dd.y, SWN[k + 1]);
                if (s0 <= th) {
                    u32 pos = atomicAdd(QCNT, 1u);
                    if (pos < QCAP) QUE[pos] = ((u32)row << 16) | (u32)k;
                    else SOVF[row] = 1;
                }
                if (s1 <= th) {
                    u32 pos = atomicAdd(QCNT, 1u);
                    if (pos < QCAP) QUE[pos] = ((u32)row << 16) | (u32)(k + 1);
                    else SOVF[row] = 1;
                }
            }
        }
        __syncthreads();

        // ---- exact rescore of queue (cooperative) ----
        {
            int qn = *QCNT;
            if (qn > QCAP) qn = QCAP;
            for (int i = tid; i < qn; i += NTHREADS) {
                u32 e = QUE[i];
                int row = e >> 16;
                int k   = e & 0xffff;
                float d = exact_d_g(xbase + row, weight + (size_t)k * DDIM,
                                    SX[row], SWN[k]);
                u64 key = ((u64)__float_as_uint(d) << 16) | (u64)k;
                atomicMin(&KEY[row], key);
            }
        }
        __syncthreads();

        // ---- epilogue: 4 threads per row (c split by 16) ----
        {
            const int row = tid & 127;
            const int c0  = (tid >> 7) * 16;
            const float* xg = xbase + row;
            const float sxr = SX[row];

            int bidx;
            if (SOVF[row]) {   // overflow fallback (never expected)
                float best = 3.4e38f; bidx = 0;
                for (int k = 0; k < KCODES; k++) {
                    float d = exact_d_g(xg, weight + (size_t)k * DDIM, sxr, SWN[k]);
                    if (d < best) { best = d; bidx = k; }
                }
            } else {
                bidx = (int)(KEY[row] & 0xffffull);
            }

            const float* qrow = weight + (size_t)bidx * DDIM;
            float* outp = out + (size_t)b * DDIM * HWSZ + hw0 + row;
            #pragma unroll
            for (int c = c0; c < c0 + 16; c++) {
                float x = xg[(size_t)c * HWSZ];
                float qv = qrow[c];
                float e = __fsub_rn(qv, x);
                outp[(size_t)c * HWSZ] = __fadd_rn(x, e);
                lloss_acc = fmaf(e, e, lloss_acc);
            }
        }
        __syncthreads();   // KEY/QCNT/cache reuse safe for next tile
    }

    // ---- final deterministic loss reduction (dot cache region is free) ----
    {
        float* red = (float*)(smem + OFF_S);
        red[tid] = lloss_acc;
        __syncthreads();
        #pragma unroll
        for (int st = NTHREADS / 2; st > 0; st >>= 1) {
            if (tid < st) red[tid] += red[tid + st];
            __syncthreads();
        }
        if (tid == 0) g_partials[blockIdx.x] = red[0];
    }
}

__global__ void loss_kernel(float* __restrict__ out, int out_size)
{
    __shared__ float red[256];
    const int tid = threadIdx.x;
    float s = 0.f;
    for (int i = tid; i < GRIDN; i += 256) s += g_partials[i];
    red[tid] = s;
    __syncthreads();
    #pragma unroll
    for (int st = 128; st > 0; st >>= 1) {
        if (tid < st) red[tid] += red[tid + st];
        __syncthreads();
    }
    if (tid == 0) {
        float loss = red[0] * 1.25f / (float)((long long)NTOT * DDIM);
        for (long long i = (long long)NTOT * DDIM; i < out_size; i++)
            out[i] = loss;
    }
}

extern "C" void kernel_launch(void* const* d_in, const int* in_sizes, int n_in,
                              void* d_out, int out_size)
{
    const float* input  = (const float*)d_in[0];
    const float* weight = (const float*)d_in[1];
    float* out = (float*)d_out;

    cudaFuncSetAttribute(vq_mma_kernel, cudaFuncAttributeMaxDynamicSharedMemorySize, SMEM_TOTAL);
    vq_mma_kernel<<<GRIDN, NTHREADS, SMEM_TOTAL>>>(input, weight, out);
    loss_kernel<<<1, 256>>>(out, out_size);
}

// round 10
// speedup vs baseline: 1.2918x; 1.0649x over previous
#include <cuda_runtime.h>
#include <cuda_fp16.h>

// VectorQuantizer, persistent single kernel: fp16 mma.sync (f16 accum) whose
// accumulators double as the smem dot cache; threshold scan; exact fp32
// re-score; loss finished by last CTA (no second kernel).
// inputs [32,64,64,64] f32 NCHW, weight [512,64] f32.
// out[0..N*D) = fl(x + fl(q-x)) NCHW; out[N*D..) = 1.25*mean((q-x)^2).

#define KCODES  512
#define DDIM    64
#define HWSZ    4096
#define NTOT    131072
#define TILE_M  128
#define NTILES  (NTOT / TILE_M)   // 1024
#define GRIDN   148
#define NTHREADS 512
#define QCAP    2048

typedef unsigned int u32;
typedef unsigned long long u64;

__device__ float g_partials[GRIDN];
__device__ u32   g_done = 0;

// ---- smem layout (bytes) ----
#define BSTRIDE   520                    // u32 per c2-row of codebook (conflict-free)
#define OFF_B     0                      // f16x2 codebook [32][520] = 66560 (persistent)
#define OFF_S     66560                  // fp16 dots [128][522] = 133632  (A32 aliased)
#define SROW      1044                   // bytes per dot row (261 words, gcd(261,32)=1)
#define OFF_A     OFF_S                  // fp32 x-tile [128][65] = 33280 (transient)
#define ASTRIDE   65
#define OFF_SWN   (OFF_S + 133632)       // 512 f32 = 2048 (persistent)
#define OFF_SX    (OFF_SWN + 2048)       // 128 f32 = 512
#define OFF_KEY   (OFF_SX + 512)         // 128 u64 = 1024
#define OFF_BMH   (OFF_KEY + 1024)       // 128*4 f32 = 2048
#define OFF_QCNT  (OFF_BMH + 2048)       // 16
#define OFF_OVF   (OFF_QCNT + 16)        // 128
#define OFF_QUE   (OFF_OVF + 128)        // QCAP*4 = 8192
#define SMEM_TOTAL (OFF_QUE + QCAP * 4)  // 214096

// ---- scalar helpers ----
__device__ __forceinline__ u32 h2pack(float lo, float hi) {
    u32 r; asm("cvt.rn.f16x2.f32 %0, %1, %2;" : "=r"(r) : "f"(hi), "f"(lo)); return r;
}
__device__ __forceinline__ u64 ffma2(u64 a, u64 b, u64 c) {
    u64 d; asm("fma.rn.f32x2 %0, %1, %2, %3;" : "=l"(d) : "l"(a), "l"(b), "l"(c)); return d;
}
__device__ __forceinline__ u64 fadd2(u64 a, u64 b) {
    u64 d; asm("add.rn.f32x2 %0, %1, %2;" : "=l"(d) : "l"(a), "l"(b)); return d;
}
__device__ __forceinline__ u64 pack2(float lo, float hi) {
    u64 d; asm("mov.b64 %0, {%1, %2};" : "=l"(d) : "f"(lo), "f"(hi)); return d;
}
__device__ __forceinline__ void unpack2(u64 v, float& lo, float& hi) {
    asm("mov.b64 {%0, %1}, %2;" : "=f"(lo), "=f"(hi) : "l"(v));
}

// f16 inputs, f16 accumulators (2 regs = 4 halves)
#define MMAH(c, a, b0, b1)                                                      \
    asm volatile("mma.sync.aligned.m16n8k16.row.col.f16.f16.f16.f16 "           \
                 "{%0,%1}, {%2,%3,%4,%5}, {%6,%7}, {%0,%1};"                    \
                 : "+r"((c)[0]), "+r"((c)[1])                                   \
                 : "r"((a)[0]), "r"((a)[1]), "r"((a)[2]), "r"((a)[3]),          \
                   "r"(b0), "r"(b1))

// exact fp32 score, bit-identical to the round-2 passing pipeline;
// x read strided from gmem (values identical to the staged copy).
__device__ __forceinline__ float exact_d_g(const float* __restrict__ xg,
                                           const float* __restrict__ wrow,
                                           float sx, float swn_k) {
    u64 a0 = 0ull, a1 = 0ull, a2 = 0ull, a3 = 0ull;
    #pragma unroll
    for (int j = 0; j < DDIM / 2; j += 4) {
        u64 x0 = pack2(xg[(size_t)(2*(j+0))*HWSZ],   xg[(size_t)(2*(j+0)+1)*HWSZ]);
        u64 x1 = pack2(xg[(size_t)(2*(j+1))*HWSZ],   xg[(size_t)(2*(j+1)+1)*HWSZ]);
        u64 x2 = pack2(xg[(size_t)(2*(j+2))*HWSZ],   xg[(size_t)(2*(j+2)+1)*HWSZ]);
        u64 x3 = pack2(xg[(size_t)(2*(j+3))*HWSZ],   xg[(size_t)(2*(j+3)+1)*HWSZ]);
        u64 w0 = pack2(wrow[2*(j+0)], wrow[2*(j+0)+1]);
        u64 w1 = pack2(wrow[2*(j+1)], wrow[2*(j+1)+1]);
        u64 w2 = pack2(wrow[2*(j+2)], wrow[2*(j+2)+1]);
        u64 w3 = pack2(wrow[2*(j+3)], wrow[2*(j+3)+1]);
        a0 = ffma2(x0, w0, a0);
        a1 = ffma2(x1, w1, a1);
        a2 = ffma2(x2, w2, a2);
        a3 = ffma2(x3, w3, a3);
    }
    a0 = fadd2(a0, a1);
    a2 = fadd2(a2, a3);
    a0 = fadd2(a0, a2);
    float lo, hi;
    unpack2(a0, lo, hi);
    float dot = __fadd_rn(lo, hi);
    float t = __fadd_rn(sx, swn_k);
    return __fsub_rn(t, __fmul_rn(2.0f, dot));
}

extern __shared__ char smem[];

__global__ void __launch_bounds__(NTHREADS, 1)
vq_mma_kernel(const float* __restrict__ input,
              const float* __restrict__ weight,
              float* __restrict__ out, int out_size)
{
    u32*   Bp    = (u32*)(smem + OFF_B);
    float* A32   = (float*)(smem + OFF_A);
    float* SWN   = (float*)(smem + OFF_SWN);
    float* SX    = (float*)(smem + OFF_SX);
    u64*   KEY   = (u64*)(smem + OFF_KEY);
    float* BMH   = (float*)(smem + OFF_BMH);
    u32*   QCNT  = (u32*)(smem + OFF_QCNT);
    unsigned char* SOVF = (unsigned char*)(smem + OFF_OVF);
    u32*   QUE   = (u32*)(smem + OFF_QUE);

    const int tid = threadIdx.x;

    // ---- stage B ONCE (f16 pairs, [c2][n]) + exact sequential norms ----
    {
        const int n = tid;
        const float4* wr = (const float4*)(weight + (size_t)n * DDIM);
        float s = 0.f;
        #pragma unroll
        for (int c4 = 0; c4 < DDIM / 4; c4++) {
            float4 wv = wr[c4];
            s = __fadd_rn(s, __fmul_rn(wv.x, wv.x));
            s = __fadd_rn(s, __fmul_rn(wv.y, wv.y));
            s = __fadd_rn(s, __fmul_rn(wv.z, wv.z));
            s = __fadd_rn(s, __fmul_rn(wv.w, wv.w));
            Bp[(c4 * 2 + 0) * BSTRIDE + n] = h2pack(wv.x, wv.y);
            Bp[(c4 * 2 + 1) * BSTRIDE + n] = h2pack(wv.z, wv.w);
        }
        SWN[n] = s;
    }

    // warp roles (fixed): 4 row-groups (32 rows) x 4 code-quarters (128 codes)
    const int lane  = tid & 31;
    const int g     = lane >> 2;
    const int tq    = lane & 3;
    const int w     = tid >> 5;
    const int rbase = (w >> 2) * 32;
    const int q     = w & 3;
    const int nb0   = q * 128;
    const unsigned FULL = 0xffffffffu;

    // epilogue ownership: row = tid&127, c-part = tid>>7
    const int erow = tid & 127;
    const int ec0  = (tid >> 7) * 16;

    float lloss_acc = 0.f;
    __syncthreads();

    // ================= persistent tile loop =================
    for (int t = blockIdx.x; t < NTILES; t += GRIDN) {
        const int b   = t >> 5;
        const int hw0 = (t & 31) * TILE_M;
        const float* xbase = input + (size_t)b * DDIM * HWSZ + hw0;

        if (tid < TILE_M) { KEY[tid] = ~0ull; SOVF[tid] = 0; }
        if (tid == 0) *QCNT = 0;

        // ---- stage A coalesced; keep own 16 x values in registers ----
        float xr[16];
        {
            #pragma unroll
            for (int i = 0; i < 16; i++) {
                int c = ec0 + i;
                float v = xbase[erow + (size_t)c * HWSZ];
                xr[i] = v;
                A32[erow * ASTRIDE + c] = v;
            }
        }
        __syncthreads();

        // ---- exact sequential sx from staged A (threads 0..127) ----
        if (tid < TILE_M) {
            const float* arow = A32 + tid * ASTRIDE;
            float sx = 0.f;
            #pragma unroll
            for (int c = 0; c < DDIM; c++)
                sx = __fadd_rn(sx, __fmul_rn(arow[c], arow[c]));
            SX[tid] = sx;
        }

        // ---- A fragments (f16) from transient A32 ----
        u32 afr[2][4][4];
        #pragma unroll
        for (int mt = 0; mt < 2; mt++) {
            const float* r0 = A32 + (rbase + mt * 16 + g) * ASTRIDE;
            const float* r1 = r0 + 8 * ASTRIDE;
            #pragma unroll
            for (int ks = 0; ks < 4; ks++) {
                const int k0 = ks * 16 + 2 * tq;
                afr[mt][ks][0] = h2pack(r0[k0],     r0[k0 + 1]);
                afr[mt][ks][1] = h2pack(r1[k0],     r1[k0 + 1]);
                afr[mt][ks][2] = h2pack(r0[k0 + 8], r0[k0 + 9]);
                afr[mt][ks][3] = h2pack(r1[k0 + 8], r1[k0 + 9]);
            }
        }
        __syncthreads();   // fragments + sx done before dot cache overwrites A32

        // ---- MMA pass: f16 accum = dot cache entries; track min ----
        float bmin[4] = {3.4e38f, 3.4e38f, 3.4e38f, 3.4e38f};

        #pragma unroll 1
        for (int n2 = 0; n2 < 8; n2++) {
            const int nb = nb0 + n2 * 16;
            u32 hacc[2][2][2];   // [mt][nn][reg]; reg0=row g, reg1=row g+8
            #pragma unroll
            for (int i = 0; i < 2; i++)
                #pragma unroll
                for (int j = 0; j < 2; j++) { hacc[i][j][0] = 0u; hacc[i][j][1] = 0u; }

            #pragma unroll
            for (int ks = 0; ks < 4; ks++) {
                const u32* p0 = Bp + (ks * 8 + tq) * BSTRIDE + nb + g;
                const u32* p1 = p0 + 4 * BSTRIDE;
                u32 b0a = p0[0], b0b = p0[8];
                u32 b1a = p1[0], b1b = p1[8];
                MMAH(hacc[0][0], afr[0][ks], b0a, b1a);
                MMAH(hacc[0][1], afr[0][ks], b0b, b1b);
                MMAH(hacc[1][0], afr[1][ks], b0a, b1a);
                MMAH(hacc[1][1], afr[1][ks], b0b, b1b);
            }

            float swnc[2][2];
            swnc[0][0] = SWN[nb + tq * 2];
            swnc[0][1] = SWN[nb + tq * 2 + 1];
            swnc[1][0] = SWN[nb + 8 + tq * 2];
            swnc[1][1] = SWN[nb + 8 + tq * 2 + 1];

            #pragma unroll
            for (int mt = 0; mt < 2; mt++)
            #pragma unroll
            for (int nn = 0; nn < 2; nn++)
            #pragma unroll
            for (int ep = 0; ep < 2; ep++) {
                const int s   = mt * 2 + ep;
                const int row = rbase + mt * 16 + ep * 8 + g;
                const int col = nb + nn * 8 + tq * 2;
                u32 hv = hacc[mt][nn][ep];
                *(u32*)(smem + OFF_S + row * SROW + col * 2) = hv;   // fp16 pair
                float2 dd = __half22float2(*(__half2*)&hv);
                float s0 = fmaf(-2.f, dd.x, swnc[nn][0]);
                float s1 = fmaf(-2.f, dd.y, swnc[nn][1]);
                bmin[s] = fminf(bmin[s], fminf(s0, s1));
            }
        }

        // quad-merge mins; publish per (row, quarter)
        #pragma unroll
        for (int s = 0; s < 4; s++) {
            float bm = bmin[s];
            bm = fminf(bm, __shfl_xor_sync(FULL, bm, 1));
            bm = fminf(bm, __shfl_xor_sync(FULL, bm, 2));
            if (tq == 0) {
                int row = rbase + (s >> 1) * 16 + (s & 1) * 8 + g;
                BMH[row * 4 + q] = bm;
            }
        }
        __syncthreads();

        // ---- collect pass: smem dot scan ----
        {
            const int row  = tid & 127;
            const int part = tid >> 7;
            const int ks0  = part * 128;

            float bm = fminf(fminf(BMH[row * 4 + 0], BMH[row * 4 + 1]),
                             fminf(BMH[row * 4 + 2], BMH[row * 4 + 3]));
            // margin: f16 input quant + f16 accum chain (worst-case) x2 dots
            float th = bm + fmaf(sqrtf(SX[row]), 1e-4f, 2e-3f);

            const __half2* drow = (const __half2*)(smem + OFF_S + row * SROW) + (ks0 >> 1);
            #pragma unroll 4
            for (int j = 0; j < 64; j++) {
                float2 dd = __half22float2(drow[j]);
                int k = ks0 + 2 * j;
                float s0 = fmaf(-2.f, dd.x, SWN[k]);
                float s1 = fmaf(-2.f, dd.y, SWN[k + 1]);
                if (s0 <= th) {
                    u32 pos = atomicAdd(QCNT, 1u);
                    if (pos < QCAP) QUE[pos] = ((u32)row << 16) | (u32)k;
                    else SOVF[row] = 1;
                }
                if (s1 <= th) {
                    u32 pos = atomicAdd(QCNT, 1u);
                    if (pos < QCAP) QUE[pos] = ((u32)row << 16) | (u32)(k + 1);
                    else SOVF[row] = 1;
                }
            }
        }
        __syncthreads();

        // ---- exact rescore of queue (cooperative) ----
        {
            int qn = *QCNT;
            if (qn > QCAP) qn = QCAP;
            for (int i = tid; i < qn; i += NTHREADS) {
                u32 e = QUE[i];
                int row = e >> 16;
                int k   = e & 0xffff;
                float d = exact_d_g(xbase + row, weight + (size_t)k * DDIM,
                                    SX[row], SWN[k]);
                u64 key = ((u64)__float_as_uint(d) << 16) | (u64)k;
                atomicMin(&KEY[row], key);
            }
        }
        __syncthreads();

        // ---- epilogue: x from registers ----
        {
            int bidx;
            if (SOVF[erow]) {   // overflow fallback (never expected)
                float best = 3.4e38f; bidx = 0;
                const float* xg = xbase + erow;
                for (int k = 0; k < KCODES; k++) {
                    float d = exact_d_g(xg, weight + (size_t)k * DDIM, SX[erow], SWN[k]);
                    if (d < best) { best = d; bidx = k; }
                }
            } else {
                bidx = (int)(KEY[erow] & 0xffffull);
            }

            const float* qrow = weight + (size_t)bidx * DDIM;
            float* outp = out + (size_t)b * DDIM * HWSZ + hw0 + erow;
            #pragma unroll
            for (int i = 0; i < 16; i++) {
                int c = ec0 + i;
                float x = xr[i];
                float qv = qrow[c];
                float e = __fsub_rn(qv, x);
                outp[(size_t)c * HWSZ] = __fadd_rn(x, e);
                lloss_acc = fmaf(e, e, lloss_acc);
            }
        }
        __syncthreads();   // KEY/QCNT/cache reuse safe for next tile
    }

    // ---- per-CTA loss reduction, then last CTA finishes ----
    {
        float* red = (float*)(smem + OFF_S);
        red[tid] = lloss_acc;
        __syncthreads();
        #pragma unroll
        for (int st = NTHREADS / 2; st > 0; st >>= 1) {
            if (tid < st) red[tid] += red[tid + st];
            __syncthreads();
        }
        __shared__ u32 s_last;
        if (tid == 0) {
            g_partials[blockIdx.x] = red[0];
            __threadfence();
            s_last = (atomicAdd(&g_done, 1u) == GRIDN - 1u) ? 1u : 0u;
        }
        __syncthreads();
        if (s_last && tid == 0) {
            float s = 0.f;
            for (int i = 0; i < GRIDN; i++) s += __ldcg(&g_partials[i]);
            float loss = s * 1.25f / (float)((long long)NTOT * DDIM);
            for (long long i = (long long)NTOT * DDIM; i < out_size; i++)
                out[i] = loss;
            atomicExch(&g_done, 0u);   // reset for next graph replay
        }
    }
}

extern "C" void kernel_launch(void* const* d_in, const int* in_sizes, int n_in,
                              void* d_out, int out_size)
{
    const float* input  = (const float*)d_in[0];
    const float* weight = (const float*)d_in[1];
    float* out = (float*)d_out;

    cudaFuncSetAttribute(vq_mma_kernel, cudaFuncAttributeMaxDynamicSharedMemorySize, SMEM_TOTAL);
    vq_mma_kernel<<<GRIDN, NTHREADS, SMEM_TOTAL>>>(input, weight, out, out_size);
}

// round 11
// speedup vs baseline: 1.5430x; 1.1945x over previous
#include <cuda_runtime.h>
#include <cuda_fp16.h>

// VectorQuantizer, persistent single kernel: fp16 mma.sync (f16 accum) whose
// accumulators double as the smem dot cache; vectorized threshold scan; exact
// fp32 re-score; loss finished by last CTA.
// inputs [32,64,64,64] f32 NCHW, weight [512,64] f32.
// out[0..N*D) = fl(x + fl(q-x)) NCHW; out[N*D..) = 1.25*mean((q-x)^2).

#define KCODES  512
#define DDIM    64
#define HWSZ    4096
#define NTOT    131072
#define TILE_M  128
#define NTILES  (NTOT / TILE_M)   // 1024
#define GRIDN   148
#define NTHREADS 512
#define QCAP    2048

typedef unsigned int u32;
typedef unsigned long long u64;

__device__ float g_partials[GRIDN];
__device__ u32   g_done = 0;

// ---- smem layout (bytes) ----
#define BSTRIDE   520                    // u32 per c2-row of codebook (conflict-free)
#define OFF_B     0                      // f16x2 codebook [32][520] = 66560 (persistent)
#define OFF_S     66560                  // fp16 dots [128][524] -> 128*1048 = 134144
#define SROW      1048                   // bytes per dot row (262 words; 6*lane%32 phase-distinct)
#define OFF_A     OFF_S                  // fp32 x-tile [128][65] = 33280 (transient alias)
#define ASTRIDE   65
#define OFF_SWN   (OFF_S + 134144)       // 512 f32 = 2048 (persistent)
#define OFF_SX    (OFF_SWN + 2048)       // 128 f32 = 512
#define OFF_KEY   (OFF_SX + 512)         // 128 u64 = 1024
#define OFF_BMH   (OFF_KEY + 1024)       // 128*4 f32 = 2048
#define OFF_QCNT  (OFF_BMH + 2048)       // 16
#define OFF_OVF   (OFF_QCNT + 16)        // 128
#define OFF_QUE   (OFF_OVF + 128)        // QCAP*4 = 8192
#define SMEM_TOTAL (OFF_QUE + QCAP * 4)  // 214672

// ---- scalar helpers ----
__device__ __forceinline__ u32 h2pack(float lo, float hi) {
    u32 r; asm("cvt.rn.f16x2.f32 %0, %1, %2;" : "=r"(r) : "f"(hi), "f"(lo)); return r;
}
__device__ __forceinline__ u64 ffma2(u64 a, u64 b, u64 c) {
    u64 d; asm("fma.rn.f32x2 %0, %1, %2, %3;" : "=l"(d) : "l"(a), "l"(b), "l"(c)); return d;
}
__device__ __forceinline__ u64 fadd2(u64 a, u64 b) {
    u64 d; asm("add.rn.f32x2 %0, %1, %2;" : "=l"(d) : "l"(a), "l"(b)); return d;
}
__device__ __forceinline__ u64 pack2(float lo, float hi) {
    u64 d; asm("mov.b64 %0, {%1, %2};" : "=l"(d) : "f"(lo), "f"(hi)); return d;
}
__device__ __forceinline__ void unpack2(u64 v, float& lo, float& hi) {
    asm("mov.b64 {%0, %1}, %2;" : "=f"(lo), "=f"(hi) : "l"(v));
}

// f16 inputs, f16 accumulators (2 regs = 4 halves)
#define MMAH(c, a, b0, b1)                                                      \
    asm volatile("mma.sync.aligned.m16n8k16.row.col.f16.f16.f16.f16 "           \
                 "{%0,%1}, {%2,%3,%4,%5}, {%6,%7}, {%0,%1};"                    \
                 : "+r"((c)[0]), "+r"((c)[1])                                   \
                 : "r"((a)[0]), "r"((a)[1]), "r"((a)[2]), "r"((a)[3]),          \
                   "r"(b0), "r"(b1))

// exact fp32 score, bit-identical to the round-2 passing pipeline;
// x read strided from gmem (values identical to the staged copy).
__device__ __forceinline__ float exact_d_g(const float* __restrict__ xg,
                                           const float* __restrict__ wrow,
                                           float sx, float swn_k) {
    u64 a0 = 0ull, a1 = 0ull, a2 = 0ull, a3 = 0ull;
    #pragma unroll
    for (int j = 0; j < DDIM / 2; j += 4) {
        u64 x0 = pack2(xg[(size_t)(2*(j+0))*HWSZ],   xg[(size_t)(2*(j+0)+1)*HWSZ]);
        u64 x1 = pack2(xg[(size_t)(2*(j+1))*HWSZ],   xg[(size_t)(2*(j+1)+1)*HWSZ]);
        u64 x2 = pack2(xg[(size_t)(2*(j+2))*HWSZ],   xg[(size_t)(2*(j+2)+1)*HWSZ]);
        u64 x3 = pack2(xg[(size_t)(2*(j+3))*HWSZ],   xg[(size_t)(2*(j+3)+1)*HWSZ]);
        u64 w0 = pack2(wrow[2*(j+0)], wrow[2*(j+0)+1]);
        u64 w1 = pack2(wrow[2*(j+1)], wrow[2*(j+1)+1]);
        u64 w2 = pack2(wrow[2*(j+2)], wrow[2*(j+2)+1]);
        u64 w3 = pack2(wrow[2*(j+3)], wrow[2*(j+3)+1]);
        a0 = ffma2(x0, w0, a0);
        a1 = ffma2(x1, w1, a1);
        a2 = ffma2(x2, w2, a2);
        a3 = ffma2(x3, w3, a3);
    }
    a0 = fadd2(a0, a1);
    a2 = fadd2(a2, a3);
    a0 = fadd2(a0, a2);
    float lo, hi;
    unpack2(a0, lo, hi);
    float dot = __fadd_rn(lo, hi);
    float t = __fadd_rn(sx, swn_k);
    return __fsub_rn(t, __fmul_rn(2.0f, dot));
}

extern __shared__ char smem[];

__global__ void __launch_bounds__(NTHREADS, 1)
vq_mma_kernel(const float* __restrict__ input,
              const float* __restrict__ weight,
              float* __restrict__ out, int out_size)
{
    u32*   Bp    = (u32*)(smem + OFF_B);
    float* A32   = (float*)(smem + OFF_A);
    float* SWN   = (float*)(smem + OFF_SWN);
    float* SX    = (float*)(smem + OFF_SX);
    u64*   KEY   = (u64*)(smem + OFF_KEY);
    float* BMH   = (float*)(smem + OFF_BMH);
    u32*   QCNT  = (u32*)(smem + OFF_QCNT);
    unsigned char* SOVF = (unsigned char*)(smem + OFF_OVF);
    u32*   QUE   = (u32*)(smem + OFF_QUE);

    const int tid = threadIdx.x;

    // ---- stage B ONCE (f16 pairs, [c2][n]) + exact sequential norms ----
    {
        const int n = tid;
        const float4* wr = (const float4*)(weight + (size_t)n * DDIM);
        float s = 0.f;
        #pragma unroll
        for (int c4 = 0; c4 < DDIM / 4; c4++) {
            float4 wv = wr[c4];
            s = __fadd_rn(s, __fmul_rn(wv.x, wv.x));
            s = __fadd_rn(s, __fmul_rn(wv.y, wv.y));
            s = __fadd_rn(s, __fmul_rn(wv.z, wv.z));
            s = __fadd_rn(s, __fmul_rn(wv.w, wv.w));
            Bp[(c4 * 2 + 0) * BSTRIDE + n] = h2pack(wv.x, wv.y);
            Bp[(c4 * 2 + 1) * BSTRIDE + n] = h2pack(wv.z, wv.w);
        }
        SWN[n] = s;
    }

    // warp roles (fixed): 4 row-groups (32 rows) x 4 code-quarters (128 codes)
    const int lane  = tid & 31;
    const int g     = lane >> 2;
    const int tq    = lane & 3;
    const int w     = tid >> 5;
    const int rbase = (w >> 2) * 32;
    const int q     = w & 3;
    const int nb0   = q * 128;
    const unsigned FULL = 0xffffffffu;

    // epilogue ownership: row = tid&127, c-part = tid>>7
    const int erow = tid & 127;
    const int ec0  = (tid >> 7) * 16;

    float lloss_acc = 0.f;
    __syncthreads();

    // ================= persistent tile loop =================
    for (int t = blockIdx.x; t < NTILES; t += GRIDN) {
        const int b   = t >> 5;
        const int hw0 = (t & 31) * TILE_M;
        const float* xbase = input + (size_t)b * DDIM * HWSZ + hw0;

        if (tid < TILE_M) { KEY[tid] = ~0ull; SOVF[tid] = 0; }
        if (tid == 0) *QCNT = 0;

        // ---- stage A coalesced; keep own 16 x values in registers ----
        float xr[16];
        {
            #pragma unroll
            for (int i = 0; i < 16; i++) {
                int c = ec0 + i;
                float v = xbase[erow + (size_t)c * HWSZ];
                xr[i] = v;
                A32[erow * ASTRIDE + c] = v;
            }
        }
        __syncthreads();

        // ---- exact sequential sx from staged A (threads 0..127) ----
        if (tid < TILE_M) {
            const float* arow = A32 + tid * ASTRIDE;
            float sx = 0.f;
            #pragma unroll
            for (int c = 0; c < DDIM; c++)
                sx = __fadd_rn(sx, __fmul_rn(arow[c], arow[c]));
            SX[tid] = sx;
        }

        // ---- A fragments (f16) from transient A32 ----
        u32 afr[2][4][4];
        #pragma unroll
        for (int mt = 0; mt < 2; mt++) {
            const float* r0 = A32 + (rbase + mt * 16 + g) * ASTRIDE;
            const float* r1 = r0 + 8 * ASTRIDE;
            #pragma unroll
            for (int ks = 0; ks < 4; ks++) {
                const int k0 = ks * 16 + 2 * tq;
                afr[mt][ks][0] = h2pack(r0[k0],     r0[k0 + 1]);
                afr[mt][ks][1] = h2pack(r1[k0],     r1[k0 + 1]);
                afr[mt][ks][2] = h2pack(r0[k0 + 8], r0[k0 + 9]);
                afr[mt][ks][3] = h2pack(r1[k0 + 8], r1[k0 + 9]);
            }
        }
        __syncthreads();   // fragments + sx done before dot cache overwrites A32

        // ---- MMA pass: f16 accum = dot cache entries; track min ----
        float bmin[4] = {3.4e38f, 3.4e38f, 3.4e38f, 3.4e38f};

        #pragma unroll 1
        for (int n2 = 0; n2 < 8; n2++) {
            const int nb = nb0 + n2 * 16;
            u32 hacc[2][2][2];   // [mt][nn][reg]; reg0=row g, reg1=row g+8
            #pragma unroll
            for (int i = 0; i < 2; i++)
                #pragma unroll
                for (int j = 0; j < 2; j++) { hacc[i][j][0] = 0u; hacc[i][j][1] = 0u; }

            #pragma unroll
            for (int ks = 0; ks < 4; ks++) {
                const u32* p0 = Bp + (ks * 8 + tq) * BSTRIDE + nb + g;
                const u32* p1 = p0 + 4 * BSTRIDE;
                u32 b0a = p0[0], b0b = p0[8];
                u32 b1a = p1[0], b1b = p1[8];
                MMAH(hacc[0][0], afr[0][ks], b0a, b1a);
                MMAH(hacc[0][1], afr[0][ks], b0b, b1b);
                MMAH(hacc[1][0], afr[1][ks], b0a, b1a);
                MMAH(hacc[1][1], afr[1][ks], b0b, b1b);
            }

            float swnc[2][2];
            swnc[0][0] = SWN[nb + tq * 2];
            swnc[0][1] = SWN[nb + tq * 2 + 1];
            swnc[1][0] = SWN[nb + 8 + tq * 2];
            swnc[1][1] = SWN[nb + 8 + tq * 2 + 1];

            #pragma unroll
            for (int mt = 0; mt < 2; mt++)
            #pragma unroll
            for (int nn = 0; nn < 2; nn++)
            #pragma unroll
            for (int ep = 0; ep < 2; ep++) {
                const int s   = mt * 2 + ep;
                const int row = rbase + mt * 16 + ep * 8 + g;
                const int col = nb + nn * 8 + tq * 2;
                u32 hv = hacc[mt][nn][ep];
                *(u32*)(smem + OFF_S + row * SROW + col * 2) = hv;   // fp16 pair
                float2 dd = __half22float2(*(__half2*)&hv);
                float s0 = fmaf(-2.f, dd.x, swnc[nn][0]);
                float s1 = fmaf(-2.f, dd.y, swnc[nn][1]);
                bmin[s] = fminf(bmin[s], fminf(s0, s1));
            }
        }

        // quad-merge mins; publish per (row, quarter)
        #pragma unroll
        for (int s = 0; s < 4; s++) {
            float bm = bmin[s];
            bm = fminf(bm, __shfl_xor_sync(FULL, bm, 1));
            bm = fminf(bm, __shfl_xor_sync(FULL, bm, 2));
            if (tq == 0) {
                int row = rbase + (s >> 1) * 16 + (s & 1) * 8 + g;
                BMH[row * 4 + q] = bm;
            }
        }
        __syncthreads();

        // ---- collect pass: vectorized smem dot scan (LDS.64, conflict-free) ----
        {
            const int row  = tid & 127;
            const int part = tid >> 7;
            const int ks0  = part * 128;

            float bm = fminf(fminf(BMH[row * 4 + 0], BMH[row * 4 + 1]),
                             fminf(BMH[row * 4 + 2], BMH[row * 4 + 3]));
            // margin: f16 input quant + f16 accum chain (worst-case) x2 dots
            float th = bm + fmaf(sqrtf(SX[row]), 1e-4f, 2e-3f);

            const uint2* drow2 = (const uint2*)(smem + OFF_S + row * SROW + ks0 * 2);
            #pragma unroll 4
            for (int j = 0; j < 32; j++) {
                uint2 v = drow2[j];
                int k = ks0 + j * 4;
                float2 da = __half22float2(*(__half2*)&v.x);
                float2 db = __half22float2(*(__half2*)&v.y);
                float s0 = fmaf(-2.f, da.x, SWN[k]);
                float s1 = fmaf(-2.f, da.y, SWN[k + 1]);
                float s2 = fmaf(-2.f, db.x, SWN[k + 2]);
                float s3 = fmaf(-2.f, db.y, SWN[k + 3]);
                if (s0 <= th) {
                    u32 pos = atomicAdd(QCNT, 1u);
                    if (pos < QCAP) QUE[pos] = ((u32)row << 16) | (u32)k;
                    else SOVF[row] = 1;
                }
                if (s1 <= th) {
                    u32 pos = atomicAdd(QCNT, 1u);
                    if (pos < QCAP) QUE[pos] = ((u32)row << 16) | (u32)(k + 1);
                    else SOVF[row] = 1;
                }
                if (s2 <= th) {
                    u32 pos = atomicAdd(QCNT, 1u);
                    if (pos < QCAP) QUE[pos] = ((u32)row << 16) | (u32)(k + 2);
                    else SOVF[row] = 1;
                }
                if (s3 <= th) {
                    u32 pos = atomicAdd(QCNT, 1u);
                    if (pos < QCAP) QUE[pos] = ((u32)row << 16) | (u32)(k + 3);
                    else SOVF[row] = 1;
                }
            }
        }
        __syncthreads();

        // ---- exact rescore of queue (cooperative) ----
        {
            int qn = *QCNT;
            if (qn > QCAP) qn = QCAP;
            for (int i = tid; i < qn; i += NTHREADS) {
                u32 e = QUE[i];
                int row = e >> 16;
                int k   = e & 0xffff;
                float d = exact_d_g(xbase + row, weight + (size_t)k * DDIM,
                                    SX[row], SWN[k]);
                u64 key = ((u64)__float_as_uint(d) << 16) | (u64)k;
                atomicMin(&KEY[row], key);
            }
        }
        __syncthreads();

        // ---- epilogue: x from registers, codeword via float4 gather ----
        {
            int bidx;
            if (SOVF[erow]) {   // overflow fallback (never expected)
                float best = 3.4e38f; bidx = 0;
                const float* xg = xbase + erow;
                for (int k = 0; k < KCODES; k++) {
                    float d = exact_d_g(xg, weight + (size_t)k * DDIM, SX[erow], SWN[k]);
                    if (d < best) { best = d; bidx = k; }
                }
            } else {
                bidx = (int)(KEY[erow] & 0xffffull);
            }

            const float4* q4 = (const float4*)(weight + (size_t)bidx * DDIM + ec0);
            float* outp = out + (size_t)b * DDIM * HWSZ + hw0 + erow;
            #pragma unroll
            for (int i4 = 0; i4 < 4; i4++) {
                float4 qv = q4[i4];
                const float qvv[4] = {qv.x, qv.y, qv.z, qv.w};
                #pragma unroll
                for (int j = 0; j < 4; j++) {
                    int i = i4 * 4 + j;
                    float x = xr[i];
                    float e = __fsub_rn(qvv[j], x);
                    outp[(size_t)(ec0 + i) * HWSZ] = __fadd_rn(x, e);
                    lloss_acc = fmaf(e, e, lloss_acc);
                }
            }
        }
        __syncthreads();   // KEY/QCNT/cache reuse safe for next tile
    }

    // ---- per-CTA loss reduction, then last CTA finishes ----
    {
        float* red = (float*)(smem + OFF_S);
        red[tid] = lloss_acc;
        __syncthreads();
        #pragma unroll
        for (int st = NTHREADS / 2; st > 0; st >>= 1) {
            if (tid < st) red[tid] += red[tid + st];
            __syncthreads();
        }
        __shared__ u32 s_last;
        if (tid == 0) {
            g_partials[blockIdx.x] = red[0];
            __threadfence();
            s_last = (atomicAdd(&g_done, 1u) == GRIDN - 1u) ? 1u : 0u;
        }
        __syncthreads();
        if (s_last && tid == 0) {
            float s = 0.f;
            for (int i = 0; i < GRIDN; i++) s += __ldcg(&g_partials[i]);
            float loss = s * 1.25f / (float)((long long)NTOT * DDIM);
            for (long long i = (long long)NTOT * DDIM; i < out_size; i++)
                out[i] = loss;
            atomicExch(&g_done, 0u);   // reset for next graph replay
        }
    }
}

extern "C" void kernel_launch(void* const* d_in, const int* in_sizes, int n_in,
                              void* d_out, int out_size)
{
    const float* input  = (const float*)d_in[0];
    const float* weight = (const float*)d_in[1];
    float* out = (float*)d_out;

    cudaFuncSetAttribute(vq_mma_kernel, cudaFuncAttributeMaxDynamicSharedMemorySize, SMEM_TOTAL);
    vq_mma_kernel<<<GRIDN, NTHREADS, SMEM_TOTAL>>>(input, weight, out, out_size);
}

// round 12
// speedup vs baseline: 1.5617x; 1.0122x over previous
#include <cuda_runtime.h>
#include <cuda_fp16.h>

// VectorQuantizer, persistent 2-CTA/SM kernel: two-pass fp16 mma.sync
// (pass1 min, pass2 bit-identical recompute + ballot collect), exact fp32
// re-score from smem x; loss finished by last CTA.
// inputs [32,64,64,64] f32 NCHW, weight [512,64] f32.
// out[0..N*D) = fl(x + fl(q-x)) NCHW; out[N*D..) = 1.25*mean((q-x)^2).

#define KCODES  512
#define DDIM    64
#define HWSZ    4096
#define NTOT    131072
#define TILE_M  128
#define NTILES  (NTOT / TILE_M)   // 1024
#define GRIDN   296               // 2 CTAs per SM
#define NTHREADS 512
#define QCAP    1024

typedef unsigned int u32;
typedef unsigned long long u64;

__device__ float g_partials[GRIDN];
__device__ u32   g_done = 0;

// ---- smem layout (bytes) ----
#define BSTRIDE   520                    // u32 per c2-row of codebook (conflict-free)
#define OFF_B     0                      // f16x2 codebook [32][520] = 66560 (persistent)
#define OFF_A     66560                  // fp32 x-tile [128][65] = 33280 (persistent per tile)
#define ASTRIDE   65
#define OFF_SWN   (OFF_A + 33280)        // 512 f32 = 2048 (persistent)
#define OFF_SX    (OFF_SWN + 2048)       // 128 f32 = 512
#define OFF_KEY   (OFF_SX + 512)         // 128 u64 = 1024
#define OFF_BMH   (OFF_KEY + 1024)       // 128*4 f32 = 2048
#define OFF_QCNT  (OFF_BMH + 2048)       // 16
#define OFF_OVF   (OFF_QCNT + 16)        // 128
#define OFF_QUE   (OFF_OVF + 128)        // QCAP*4 = 4096
#define SMEM_TOTAL (OFF_QUE + QCAP * 4)  // 109712  (2 per SM: 219424 < 227328)

// ---- scalar helpers ----
__device__ __forceinline__ u32 h2pack(float lo, float hi) {
    u32 r; asm("cvt.rn.f16x2.f32 %0, %1, %2;" : "=r"(r) : "f"(hi), "f"(lo)); return r;
}
__device__ __forceinline__ u64 ffma2(u64 a, u64 b, u64 c) {
    u64 d; asm("fma.rn.f32x2 %0, %1, %2, %3;" : "=l"(d) : "l"(a), "l"(b), "l"(c)); return d;
}
__device__ __forceinline__ u64 fadd2(u64 a, u64 b) {
    u64 d; asm("add.rn.f32x2 %0, %1, %2;" : "=l"(d) : "l"(a), "l"(b)); return d;
}
__device__ __forceinline__ u64 pack2(float lo, float hi) {
    u64 d; asm("mov.b64 %0, {%1, %2};" : "=l"(d) : "f"(lo), "f"(hi)); return d;
}
__device__ __forceinline__ void unpack2(u64 v, float& lo, float& hi) {
    asm("mov.b64 {%0, %1}, %2;" : "=f"(lo), "=f"(hi) : "l"(v));
}

// f16 inputs, f16 accumulators (2 regs = 4 halves)
#define MMAH(c, a, b0, b1)                                                      \
    asm volatile("mma.sync.aligned.m16n8k16.row.col.f16.f16.f16.f16 "           \
                 "{%0,%1}, {%2,%3,%4,%5}, {%6,%7}, {%0,%1};"                    \
                 : "+r"((c)[0]), "+r"((c)[1])                                   \
                 : "r"((a)[0]), "r"((a)[1]), "r"((a)[2]), "r"((a)[3]),          \
                   "r"(b0), "r"(b1))

// exact fp32 score, bit-identical FP sequence to the round-2 passing pipeline;
// x read from smem row (values identical to gmem).
__device__ __forceinline__ float exact_d_s(const float* __restrict__ xrow,
                                           const float* __restrict__ wrow,
                                           float sx, float swn_k) {
    u64 a0 = 0ull, a1 = 0ull, a2 = 0ull, a3 = 0ull;
    #pragma unroll
    for (int j = 0; j < DDIM / 2; j += 4) {
        u64 x0 = pack2(xrow[2*(j+0)], xrow[2*(j+0)+1]);
        u64 x1 = pack2(xrow[2*(j+1)], xrow[2*(j+1)+1]);
        u64 x2 = pack2(xrow[2*(j+2)], xrow[2*(j+2)+1]);
        u64 x3 = pack2(xrow[2*(j+3)], xrow[2*(j+3)+1]);
        u64 w0 = pack2(wrow[2*(j+0)], wrow[2*(j+0)+1]);
        u64 w1 = pack2(wrow[2*(j+1)], wrow[2*(j+1)+1]);
        u64 w2 = pack2(wrow[2*(j+2)], wrow[2*(j+2)+1]);
        u64 w3 = pack2(wrow[2*(j+3)], wrow[2*(j+3)+1]);
        a0 = ffma2(x0, w0, a0);
        a1 = ffma2(x1, w1, a1);
        a2 = ffma2(x2, w2, a2);
        a3 = ffma2(x3, w3, a3);
    }
    a0 = fadd2(a0, a1);
    a2 = fadd2(a2, a3);
    a0 = fadd2(a0, a2);
    float lo, hi;
    unpack2(a0, lo, hi);
    float dot = __fadd_rn(lo, hi);
    float t = __fadd_rn(sx, swn_k);
    return __fsub_rn(t, __fmul_rn(2.0f, dot));
}

extern __shared__ char smem[];

__global__ void __launch_bounds__(NTHREADS, 2)
vq_mma_kernel(const float* __restrict__ input,
              const float* __restrict__ weight,
              float* __restrict__ out, int out_size)
{
    u32*   Bp    = (u32*)(smem + OFF_B);
    float* A32   = (float*)(smem + OFF_A);
    float* SWN   = (float*)(smem + OFF_SWN);
    float* SX    = (float*)(smem + OFF_SX);
    u64*   KEY   = (u64*)(smem + OFF_KEY);
    float* BMH   = (float*)(smem + OFF_BMH);
    u32*   QCNT  = (u32*)(smem + OFF_QCNT);
    unsigned char* SOVF = (unsigned char*)(smem + OFF_OVF);
    u32*   QUE   = (u32*)(smem + OFF_QUE);

    const int tid = threadIdx.x;

    // ---- stage B ONCE (f16 pairs, [c2][n]) + exact sequential norms ----
    {
        const int n = tid;
        const float4* wr = (const float4*)(weight + (size_t)n * DDIM);
        float s = 0.f;
        #pragma unroll
        for (int c4 = 0; c4 < DDIM / 4; c4++) {
            float4 wv = wr[c4];
            s = __fadd_rn(s, __fmul_rn(wv.x, wv.x));
            s = __fadd_rn(s, __fmul_rn(wv.y, wv.y));
            s = __fadd_rn(s, __fmul_rn(wv.z, wv.z));
            s = __fadd_rn(s, __fmul_rn(wv.w, wv.w));
            Bp[(c4 * 2 + 0) * BSTRIDE + n] = h2pack(wv.x, wv.y);
            Bp[(c4 * 2 + 1) * BSTRIDE + n] = h2pack(wv.z, wv.w);
        }
        SWN[n] = s;
    }

    // warp roles: 4 row-groups (32 rows) x 4 code-quarters (128 codes)
    const int lane  = tid & 31;
    const int g     = lane >> 2;
    const int tq    = lane & 3;
    const int w     = tid >> 5;
    const int rbase = (w >> 2) * 32;
    const int q     = w & 3;
    const int nb0   = q * 128;
    const unsigned FULL = 0xffffffffu;

    // staging/epilogue ownership: row = tid&127, c-part = tid>>7
    const int erow = tid & 127;
    const int ec0  = (tid >> 7) * 16;

    float lloss_acc = 0.f;
    __syncthreads();

    // ================= persistent tile loop =================
    for (int t = blockIdx.x; t < NTILES; t += GRIDN) {
        const int b   = t >> 5;
        const int hw0 = (t & 31) * TILE_M;
        const float* xbase = input + (size_t)b * DDIM * HWSZ + hw0;

        if (tid < TILE_M) { KEY[tid] = ~0ull; SOVF[tid] = 0; }
        if (tid == 0) *QCNT = 0;

        // ---- stage A coalesced into persistent A32 ----
        #pragma unroll
        for (int i = 0; i < 16; i++) {
            int c = ec0 + i;
            A32[erow * ASTRIDE + c] = xbase[erow + (size_t)c * HWSZ];
        }
        __syncthreads();

        // ---- exact sequential sx from staged A (threads 0..127) ----
        if (tid < TILE_M) {
            const float* arow = A32 + tid * ASTRIDE;
            float sx = 0.f;
            #pragma unroll
            for (int c = 0; c < DDIM; c++)
                sx = __fadd_rn(sx, __fmul_rn(arow[c], arow[c]));
            SX[tid] = sx;
        }

        // ---- A fragments (f16) from A32 ----
        u32 afr[2][4][4];
        #pragma unroll
        for (int mt = 0; mt < 2; mt++) {
            const float* r0 = A32 + (rbase + mt * 16 + g) * ASTRIDE;
            const float* r1 = r0 + 8 * ASTRIDE;
            #pragma unroll
            for (int ks = 0; ks < 4; ks++) {
                const int k0 = ks * 16 + 2 * tq;
                afr[mt][ks][0] = h2pack(r0[k0],     r0[k0 + 1]);
                afr[mt][ks][1] = h2pack(r1[k0],     r1[k0 + 1]);
                afr[mt][ks][2] = h2pack(r0[k0 + 8], r0[k0 + 9]);
                afr[mt][ks][3] = h2pack(r1[k0 + 8], r1[k0 + 9]);
            }
        }
        __syncthreads();   // sx visible to all before pass-1 threshold math

        // ================= PASS 1: min only =================
        float bmin[4] = {3.4e38f, 3.4e38f, 3.4e38f, 3.4e38f};

        #pragma unroll 1
        for (int n2 = 0; n2 < 8; n2++) {
            const int nb = nb0 + n2 * 16;
            u32 hacc[2][2][2];
            #pragma unroll
            for (int i = 0; i < 2; i++)
                #pragma unroll
                for (int j = 0; j < 2; j++) { hacc[i][j][0] = 0u; hacc[i][j][1] = 0u; }

            #pragma unroll
            for (int ks = 0; ks < 4; ks++) {
                const u32* p0 = Bp + (ks * 8 + tq) * BSTRIDE + nb + g;
                const u32* p1 = p0 + 4 * BSTRIDE;
                u32 b0a = p0[0], b0b = p0[8];
                u32 b1a = p1[0], b1b = p1[8];
                MMAH(hacc[0][0], afr[0][ks], b0a, b1a);
                MMAH(hacc[0][1], afr[0][ks], b0b, b1b);
                MMAH(hacc[1][0], afr[1][ks], b0a, b1a);
                MMAH(hacc[1][1], afr[1][ks], b0b, b1b);
            }

            float swnc[2][2];
            swnc[0][0] = SWN[nb + tq * 2];
            swnc[0][1] = SWN[nb + tq * 2 + 1];
            swnc[1][0] = SWN[nb + 8 + tq * 2];
            swnc[1][1] = SWN[nb + 8 + tq * 2 + 1];

            #pragma unroll
            for (int mt = 0; mt < 2; mt++)
            #pragma unroll
            for (int nn = 0; nn < 2; nn++)
            #pragma unroll
            for (int ep = 0; ep < 2; ep++) {
                const int s = mt * 2 + ep;
                float2 dd = __half22float2(*(__half2*)&hacc[mt][nn][ep]);
                float s0 = fmaf(-2.f, dd.x, swnc[nn][0]);
                float s1 = fmaf(-2.f, dd.y, swnc[nn][1]);
                bmin[s] = fminf(bmin[s], fminf(s0, s1));
            }
        }

        // quad-merge mins; publish per (row, quarter)
        #pragma unroll
        for (int s = 0; s < 4; s++) {
            float bm = bmin[s];
            bm = fminf(bm, __shfl_xor_sync(FULL, bm, 1));
            bm = fminf(bm, __shfl_xor_sync(FULL, bm, 2));
            if (tq == 0) {
                int row = rbase + (s >> 1) * 16 + (s & 1) * 8 + g;
                BMH[row * 4 + q] = bm;
            }
        }
        __syncthreads();

        // thresholds (margin: f16 input quant + f16 accum chain, x2 dots)
        float th[4];
        #pragma unroll
        for (int s = 0; s < 4; s++) {
            int row = rbase + (s >> 1) * 16 + (s & 1) * 8 + g;
            float bm = fminf(fminf(BMH[row * 4 + 0], BMH[row * 4 + 1]),
                             fminf(BMH[row * 4 + 2], BMH[row * 4 + 3]));
            th[s] = bm + fmaf(sqrtf(SX[row]), 1e-4f, 2e-3f);
        }

        // ================= PASS 2: bit-identical recompute + collect =========
        #pragma unroll 1
        for (int n2 = 0; n2 < 8; n2++) {
            const int nb = nb0 + n2 * 16;
            u32 hacc[2][2][2];
            #pragma unroll
            for (int i = 0; i < 2; i++)
                #pragma unroll
                for (int j = 0; j < 2; j++) { hacc[i][j][0] = 0u; hacc[i][j][1] = 0u; }

            #pragma unroll
            for (int ks = 0; ks < 4; ks++) {
                const u32* p0 = Bp + (ks * 8 + tq) * BSTRIDE + nb + g;
                const u32* p1 = p0 + 4 * BSTRIDE;
                u32 b0a = p0[0], b0b = p0[8];
                u32 b1a = p1[0], b1b = p1[8];
                MMAH(hacc[0][0], afr[0][ks], b0a, b1a);
                MMAH(hacc[0][1], afr[0][ks], b0b, b1b);
                MMAH(hacc[1][0], afr[1][ks], b0a, b1a);
                MMAH(hacc[1][1], afr[1][ks], b0b, b1b);
            }

            float swnc[2][2];
            swnc[0][0] = SWN[nb + tq * 2];
            swnc[0][1] = SWN[nb + tq * 2 + 1];
            swnc[1][0] = SWN[nb + 8 + tq * 2];
            swnc[1][1] = SWN[nb + 8 + tq * 2 + 1];

            #pragma unroll
            for (int mt = 0; mt < 2; mt++)
            #pragma unroll
            for (int nn = 0; nn < 2; nn++)
            #pragma unroll
            for (int ep = 0; ep < 2; ep++) {
                const int s   = mt * 2 + ep;
                const int row = rbase + mt * 16 + ep * 8 + g;
                const int col = nb + nn * 8 + tq * 2;
                float2 dd = __half22float2(*(__half2*)&hacc[mt][nn][ep]);
                float s0 = fmaf(-2.f, dd.x, swnc[nn][0]);
                float s1 = fmaf(-2.f, dd.y, swnc[nn][1]);
                #pragma unroll
                for (int e = 0; e < 2; e++) {
                    bool take = ((e ? s1 : s0) <= th[s]);
                    unsigned m = __ballot_sync(FULL, take);
                    if (m) {
                        int leader = __ffs(m) - 1;
                        u32 base = 0;
                        if (lane == leader) base = atomicAdd(QCNT, (u32)__popc(m));
                        base = __shfl_sync(FULL, base, leader);
                        if (take) {
                            u32 pos = base + (u32)__popc(m & ((1u << lane) - 1u));
                            if (pos < QCAP) QUE[pos] = ((u32)row << 16) | (u32)(col + e);
                            else SOVF[row] = 1;
                        }
                    }
                }
            }
        }
        __syncthreads();

        // ---- exact rescore of queue (x from smem) ----
        {
            int qn = *QCNT;
            if (qn > QCAP) qn = QCAP;
            for (int i = tid; i < qn; i += NTHREADS) {
                u32 e = QUE[i];
                int row = e >> 16;
                int k   = e & 0xffff;
                float d = exact_d_s(A32 + row * ASTRIDE, weight + (size_t)k * DDIM,
                                    SX[row], SWN[k]);
                u64 key = ((u64)__float_as_uint(d) << 16) | (u64)k;
                atomicMin(&KEY[row], key);
            }
        }
        __syncthreads();

        // ---- epilogue: x from A32, codeword via float4 gather ----
        {
            int bidx;
            if (SOVF[erow]) {   // overflow fallback (never expected)
                float best = 3.4e38f; bidx = 0;
                for (int k = 0; k < KCODES; k++) {
                    float d = exact_d_s(A32 + erow * ASTRIDE, weight + (size_t)k * DDIM,
                                        SX[erow], SWN[k]);
                    if (d < best) { best = d; bidx = k; }
                }
            } else {
                bidx = (int)(KEY[erow] & 0xffffull);
            }

            const float4* q4 = (const float4*)(weight + (size_t)bidx * DDIM + ec0);
            const float* arow = A32 + erow * ASTRIDE + ec0;
            float* outp = out + (size_t)b * DDIM * HWSZ + hw0 + erow;
            #pragma unroll
            for (int i4 = 0; i4 < 4; i4++) {
                float4 qv = q4[i4];
                const float qvv[4] = {qv.x, qv.y, qv.z, qv.w};
                #pragma unroll
                for (int j = 0; j < 4; j++) {
                    int i = i4 * 4 + j;
                    float x = arow[i];
                    float e = __fsub_rn(qvv[j], x);
                    outp[(size_t)(ec0 + i) * HWSZ] = __fadd_rn(x, e);
                    lloss_acc = fmaf(e, e, lloss_acc);
                }
            }
        }
        __syncthreads();   // A32/KEY/QCNT reuse safe for next tile
    }

    // ---- per-CTA loss reduction, then last CTA finishes ----
    {
        float* red = (float*)(smem + OFF_A);
        red[tid] = lloss_acc;
        __syncthreads();
        #pragma unroll
        for (int st = NTHREADS / 2; st > 0; st >>= 1) {
            if (tid < st) red[tid] += red[tid + st];
            __syncthreads();
        }
        __shared__ u32 s_last;
        if (tid == 0) {
            g_partials[blockIdx.x] = red[0];
            __threadfence();
            s_last = (atomicAdd(&g_done, 1u) == GRIDN - 1u) ? 1u : 0u;
        }
        __syncthreads();
        if (s_last && tid == 0) {
            float s = 0.f;
            for (int i = 0; i < GRIDN; i++) s += __ldcg(&g_partials[i]);
            float loss = s * 1.25f / (float)((long long)NTOT * DDIM);
            for (long long i = (long long)NTOT * DDIM; i < out_size; i++)
                out[i] = loss;
            atomicExch(&g_done, 0u);   // reset for next graph replay
        }
    }
}

extern "C" void kernel_launch(void* const* d_in, const int* in_sizes, int n_in,
                              void* d_out, int out_size)
{
    const float* input  = (const float*)d_in[0];
    const float* weight = (const float*)d_in[1];
    float* out = (float*)d_out;

    cudaFuncSetAttribute(vq_mma_kernel, cudaFuncAttributeMaxDynamicSharedMemorySize, SMEM_TOTAL);
    vq_mma_kernel<<<GRIDN, NTHREADS, SMEM_TOTAL>>>(input, weight, out, out_size);
}

// round 13
// speedup vs baseline: 1.6212x; 1.0381x over previous
#include <cuda_runtime.h>
#include <cuda_fp16.h>

// VectorQuantizer, persistent 2-CTA/SM kernel: two-pass fp16 mma.sync with
// K-permuted operand layout (float4 A-fragment loads), ballot collect, exact
// fp32 re-score from smem x; loss finished by last CTA.
// inputs [32,64,64,64] f32 NCHW, weight [512,64] f32.
// out[0..N*D) = fl(x + fl(q-x)) NCHW; out[N*D..) = 1.25*mean((q-x)^2).

#define KCODES  512
#define DDIM    64
#define HWSZ    4096
#define NTOT    131072
#define TILE_M  128
#define NTILES  (NTOT / TILE_M)   // 1024
#define GRIDN   296               // 2 CTAs per SM
#define NTHREADS 512
#define QCAP    1024

typedef unsigned int u32;
typedef unsigned long long u64;

__device__ float g_partials[GRIDN];
__device__ u32   g_done = 0;

// ---- smem layout (bytes) ----
#define BSTRIDE   520                    // u32 per k-pair row of codebook (conflict-free)
#define OFF_B     0                      // f16x2 codebook [32][520] = 66560 (persistent)
#define OFF_A     66560                  // fp32 x-tile [128][68] = 34816 (16B-aligned rows)
#define ASTRIDE   68
#define OFF_SWN   (OFF_A + 34816)        // 512 f32 = 2048 (persistent)
#define OFF_SX    (OFF_SWN + 2048)       // 128 f32 = 512
#define OFF_KEY   (OFF_SX + 512)         // 128 u64 = 1024
#define OFF_BMH   (OFF_KEY + 1024)       // 128*4 f32 = 2048
#define OFF_QCNT  (OFF_BMH + 2048)       // 16
#define OFF_OVF   (OFF_QCNT + 16)        // 128
#define OFF_QUE   (OFF_OVF + 128)        // QCAP*4 = 4096
#define SMEM_TOTAL (OFF_QUE + QCAP * 4)  // 111248  (2 per SM < 227KB)

// ---- scalar helpers ----
__device__ __forceinline__ u32 h2pack(float lo, float hi) {
    u32 r; asm("cvt.rn.f16x2.f32 %0, %1, %2;" : "=r"(r) : "f"(hi), "f"(lo)); return r;
}
__device__ __forceinline__ u64 ffma2(u64 a, u64 b, u64 c) {
    u64 d; asm("fma.rn.f32x2 %0, %1, %2, %3;" : "=l"(d) : "l"(a), "l"(b), "l"(c)); return d;
}
__device__ __forceinline__ u64 fadd2(u64 a, u64 b) {
    u64 d; asm("add.rn.f32x2 %0, %1, %2;" : "=l"(d) : "l"(a), "l"(b)); return d;
}
__device__ __forceinline__ u64 pack2(float lo, float hi) {
    u64 d; asm("mov.b64 %0, {%1, %2};" : "=l"(d) : "f"(lo), "f"(hi)); return d;
}
__device__ __forceinline__ void unpack2(u64 v, float& lo, float& hi) {
    asm("mov.b64 {%0, %1}, %2;" : "=f"(lo), "=f"(hi) : "l"(v));
}

// f16 inputs, f16 accumulators (2 regs = 4 halves)
#define MMAH(c, a, b0, b1)                                                      \
    asm volatile("mma.sync.aligned.m16n8k16.row.col.f16.f16.f16.f16 "           \
                 "{%0,%1}, {%2,%3,%4,%5}, {%6,%7}, {%0,%1};"                    \
                 : "+r"((c)[0]), "+r"((c)[1])                                   \
                 : "r"((a)[0]), "r"((a)[1]), "r"((a)[2]), "r"((a)[3]),          \
                   "r"(b0), "r"(b1))

// exact fp32 score, bit-identical FP sequence to the round-2 passing pipeline;
// x read from smem row (values identical to gmem; logical c order).
__device__ __forceinline__ float exact_d_s(const float* __restrict__ xrow,
                                           const float* __restrict__ wrow,
                                           float sx, float swn_k) {
    u64 a0 = 0ull, a1 = 0ull, a2 = 0ull, a3 = 0ull;
    #pragma unroll
    for (int j = 0; j < DDIM / 2; j += 4) {
        u64 x0 = pack2(xrow[2*(j+0)], xrow[2*(j+0)+1]);
        u64 x1 = pack2(xrow[2*(j+1)], xrow[2*(j+1)+1]);
        u64 x2 = pack2(xrow[2*(j+2)], xrow[2*(j+2)+1]);
        u64 x3 = pack2(xrow[2*(j+3)], xrow[2*(j+3)+1]);
        u64 w0 = pack2(wrow[2*(j+0)], wrow[2*(j+0)+1]);
        u64 w1 = pack2(wrow[2*(j+1)], wrow[2*(j+1)+1]);
        u64 w2 = pack2(wrow[2*(j+2)], wrow[2*(j+2)+1]);
        u64 w3 = pack2(wrow[2*(j+3)], wrow[2*(j+3)+1]);
        a0 = ffma2(x0, w0, a0);
        a1 = ffma2(x1, w1, a1);
        a2 = ffma2(x2, w2, a2);
        a3 = ffma2(x3, w3, a3);
    }
    a0 = fadd2(a0, a1);
    a2 = fadd2(a2, a3);
    a0 = fadd2(a0, a2);
    float lo, hi;
    unpack2(a0, lo, hi);
    float dot = __fadd_rn(lo, hi);
    float t = __fadd_rn(sx, swn_k);
    return __fsub_rn(t, __fmul_rn(2.0f, dot));
}

extern __shared__ char smem[];

__global__ void __launch_bounds__(NTHREADS, 2)
vq_mma_kernel(const float* __restrict__ input,
              const float* __restrict__ weight,
              float* __restrict__ out, int out_size)
{
    u32*   Bp    = (u32*)(smem + OFF_B);
    float* A32   = (float*)(smem + OFF_A);
    float* SWN   = (float*)(smem + OFF_SWN);
    float* SX    = (float*)(smem + OFF_SX);
    u64*   KEY   = (u64*)(smem + OFF_KEY);
    float* BMH   = (float*)(smem + OFF_BMH);
    u32*   QCNT  = (u32*)(smem + OFF_QCNT);
    unsigned char* SOVF = (unsigned char*)(smem + OFF_OVF);
    u32*   QUE   = (u32*)(smem + OFF_QUE);

    const int tid = threadIdx.x;

    // ---- stage B ONCE with K-permutation pi + exact sequential norms ----
    // logical c block kb (16 ch), float4 t=c4&3 -> physical k-pair rows
    // (8kb + t) for elems {x,y} and (8kb + t + 4) for elems {z,w}.
    {
        const int n = tid;
        const float4* wr = (const float4*)(weight + (size_t)n * DDIM);
        float s = 0.f;
        #pragma unroll
        for (int c4 = 0; c4 < DDIM / 4; c4++) {
            float4 wv = wr[c4];
            s = __fadd_rn(s, __fmul_rn(wv.x, wv.x));
            s = __fadd_rn(s, __fmul_rn(wv.y, wv.y));
            s = __fadd_rn(s, __fmul_rn(wv.z, wv.z));
            s = __fadd_rn(s, __fmul_rn(wv.w, wv.w));
            const int kb = c4 >> 2, t = c4 & 3;
            Bp[(8 * kb + t)     * BSTRIDE + n] = h2pack(wv.x, wv.y);
            Bp[(8 * kb + t + 4) * BSTRIDE + n] = h2pack(wv.z, wv.w);
        }
        SWN[n] = s;
    }

    // warp roles: 4 row-groups (32 rows) x 4 code-quarters (128 codes)
    const int lane  = tid & 31;
    const int g     = lane >> 2;
    const int tq    = lane & 3;
    const int w     = tid >> 5;
    const int rbase = (w >> 2) * 32;
    const int q     = w & 3;
    const int nb0   = q * 128;
    const unsigned FULL = 0xffffffffu;

    // staging/epilogue ownership: row = tid&127, c-part = tid>>7
    const int erow = tid & 127;
    const int ec0  = (tid >> 7) * 16;

    float lloss_acc = 0.f;
    __syncthreads();

    // ================= persistent tile loop =================
    for (int t = blockIdx.x; t < NTILES; t += GRIDN) {
        const int b   = t >> 5;
        const int hw0 = (t & 31) * TILE_M;
        const float* xbase = input + (size_t)b * DDIM * HWSZ + hw0;

        if (tid < TILE_M) { KEY[tid] = ~0ull; SOVF[tid] = 0; }
        if (tid == 0) *QCNT = 0;

        // ---- stage A coalesced LDG -> float4 STS ----
        {
            float4* arow4 = (float4*)(A32 + erow * ASTRIDE);
            #pragma unroll
            for (int i4 = 0; i4 < 4; i4++) {
                int c = ec0 + i4 * 4;
                float4 v;
                v.x = xbase[erow + (size_t)(c + 0) * HWSZ];
                v.y = xbase[erow + (size_t)(c + 1) * HWSZ];
                v.z = xbase[erow + (size_t)(c + 2) * HWSZ];
                v.w = xbase[erow + (size_t)(c + 3) * HWSZ];
                arow4[(ec0 >> 2) + i4] = v;
            }
        }
        __syncthreads();

        // ---- exact sequential sx via float4 (order x,y,z,w preserved) ----
        if (tid < TILE_M) {
            const float4* a4 = (const float4*)(A32 + tid * ASTRIDE);
            float sx = 0.f;
            #pragma unroll
            for (int c4 = 0; c4 < 16; c4++) {
                float4 v = a4[c4];
                sx = __fadd_rn(sx, __fmul_rn(v.x, v.x));
                sx = __fadd_rn(sx, __fmul_rn(v.y, v.y));
                sx = __fadd_rn(sx, __fmul_rn(v.z, v.z));
                sx = __fadd_rn(sx, __fmul_rn(v.w, v.w));
            }
            SX[tid] = sx;
        }

        // ---- A fragments (f16, pi-permuted): one float4 per (mt,ks,row-half) ----
        u32 afr[2][4][4];
        #pragma unroll
        for (int mt = 0; mt < 2; mt++) {
            const float4* r0 = (const float4*)(A32 + (rbase + mt * 16 + g) * ASTRIDE);
            const float4* r1 = (const float4*)(A32 + (rbase + mt * 16 + g + 8) * ASTRIDE);
            #pragma unroll
            for (int ks = 0; ks < 4; ks++) {
                float4 v0 = r0[ks * 4 + tq];
                float4 v1 = r1[ks * 4 + tq];
                afr[mt][ks][0] = h2pack(v0.x, v0.y);   // phys k = 2tq,2tq+1   (rows g)
                afr[mt][ks][1] = h2pack(v1.x, v1.y);   //                      (rows g+8)
                afr[mt][ks][2] = h2pack(v0.z, v0.w);   // phys k = 2tq+8,2tq+9 (rows g)
                afr[mt][ks][3] = h2pack(v1.z, v1.w);   //                      (rows g+8)
            }
        }
        __syncthreads();   // sx visible to all before pass-1 threshold math

        // ================= PASS 1: min only =================
        float bmin[4] = {3.4e38f, 3.4e38f, 3.4e38f, 3.4e38f};

        #pragma unroll 1
        for (int n2 = 0; n2 < 8; n2++) {
            const int nb = nb0 + n2 * 16;
            u32 hacc[2][2][2];
            #pragma unroll
            for (int i = 0; i < 2; i++)
                #pragma unroll
                for (int j = 0; j < 2; j++) { hacc[i][j][0] = 0u; hacc[i][j][1] = 0u; }

            #pragma unroll
            for (int ks = 0; ks < 4; ks++) {
                const u32* p0 = Bp + (ks * 8 + tq) * BSTRIDE + nb + g;
                const u32* p1 = p0 + 4 * BSTRIDE;
                u32 b0a = p0[0], b0b = p0[8];
                u32 b1a = p1[0], b1b = p1[8];
                MMAH(hacc[0][0], afr[0][ks], b0a, b1a);
                MMAH(hacc[0][1], afr[0][ks], b0b, b1b);
                MMAH(hacc[1][0], afr[1][ks], b0a, b1a);
                MMAH(hacc[1][1], afr[1][ks], b0b, b1b);
            }

            float swnc[2][2];
            swnc[0][0] = SWN[nb + tq * 2];
            swnc[0][1] = SWN[nb + tq * 2 + 1];
            swnc[1][0] = SWN[nb + 8 + tq * 2];
            swnc[1][1] = SWN[nb + 8 + tq * 2 + 1];

            #pragma unroll
            for (int mt = 0; mt < 2; mt++)
            #pragma unroll
            for (int nn = 0; nn < 2; nn++)
            #pragma unroll
            for (int ep = 0; ep < 2; ep++) {
                const int s = mt * 2 + ep;
                float2 dd = __half22float2(*(__half2*)&hacc[mt][nn][ep]);
                float s0 = fmaf(-2.f, dd.x, swnc[nn][0]);
                float s1 = fmaf(-2.f, dd.y, swnc[nn][1]);
                bmin[s] = fminf(bmin[s], fminf(s0, s1));
            }
        }

        // quad-merge mins; publish per (row, quarter)
        #pragma unroll
        for (int s = 0; s < 4; s++) {
            float bm = bmin[s];
            bm = fminf(bm, __shfl_xor_sync(FULL, bm, 1));
            bm = fminf(bm, __shfl_xor_sync(FULL, bm, 2));
            if (tq == 0) {
                int row = rbase + (s >> 1) * 16 + (s & 1) * 8 + g;
                BMH[row * 4 + q] = bm;
            }
        }
        __syncthreads();

        // thresholds (margin: f16 input quant + f16 accum chain, x2 dots)
        float th[4];
        #pragma unroll
        for (int s = 0; s < 4; s++) {
            int row = rbase + (s >> 1) * 16 + (s & 1) * 8 + g;
            float bm = fminf(fminf(BMH[row * 4 + 0], BMH[row * 4 + 1]),
                             fminf(BMH[row * 4 + 2], BMH[row * 4 + 3]));
            th[s] = bm + fmaf(sqrtf(SX[row]), 1e-4f, 2e-3f);
        }

        // ================= PASS 2: bit-identical recompute + collect =========
        #pragma unroll 1
        for (int n2 = 0; n2 < 8; n2++) {
            const int nb = nb0 + n2 * 16;
            u32 hacc[2][2][2];
            #pragma unroll
            for (int i = 0; i < 2; i++)
                #pragma unroll
                for (int j = 0; j < 2; j++) { hacc[i][j][0] = 0u; hacc[i][j][1] = 0u; }

            #pragma unroll
            for (int ks = 0; ks < 4; ks++) {
                const u32* p0 = Bp + (ks * 8 + tq) * BSTRIDE + nb + g;
                const u32* p1 = p0 + 4 * BSTRIDE;
                u32 b0a = p0[0], b0b = p0[8];
                u32 b1a = p1[0], b1b = p1[8];
                MMAH(hacc[0][0], afr[0][ks], b0a, b1a);
                MMAH(hacc[0][1], afr[0][ks], b0b, b1b);
                MMAH(hacc[1][0], afr[1][ks], b0a, b1a);
                MMAH(hacc[1][1], afr[1][ks], b0b, b1b);
            }

            float swnc[2][2];
            swnc[0][0] = SWN[nb + tq * 2];
            swnc[0][1] = SWN[nb + tq * 2 + 1];
            swnc[1][0] = SWN[nb + 8 + tq * 2];
            swnc[1][1] = SWN[nb + 8 + tq * 2 + 1];

            #pragma unroll
            for (int mt = 0; mt < 2; mt++)
            #pragma unroll
            for (int nn = 0; nn < 2; nn++)
            #pragma unroll
            for (int ep = 0; ep < 2; ep++) {
                const int s   = mt * 2 + ep;
                const int row = rbase + mt * 16 + ep * 8 + g;
                const int col = nb + nn * 8 + tq * 2;
                float2 dd = __half22float2(*(__half2*)&hacc[mt][nn][ep]);
                float s0 = fmaf(-2.f, dd.x, swnc[nn][0]);
                float s1 = fmaf(-2.f, dd.y, swnc[nn][1]);
                #pragma unroll
                for (int e = 0; e < 2; e++) {
                    bool take = ((e ? s1 : s0) <= th[s]);
                    unsigned m = __ballot_sync(FULL, take);
                    if (m) {
                        int leader = __ffs(m) - 1;
                        u32 base = 0;
                        if (lane == leader) base = atomicAdd(QCNT, (u32)__popc(m));
                        base = __shfl_sync(FULL, base, leader);
                        if (take) {
                            u32 pos = base + (u32)__popc(m & ((1u << lane) - 1u));
                            if (pos < QCAP) QUE[pos] = ((u32)row << 16) | (u32)(col + e);
                            else SOVF[row] = 1;
                        }
                    }
                }
            }
        }
        __syncthreads();

        // ---- exact rescore of queue (x from smem) ----
        {
            int qn = *QCNT;
            if (qn > QCAP) qn = QCAP;
            for (int i = tid; i < qn; i += NTHREADS) {
                u32 e = QUE[i];
                int row = e >> 16;
                int k   = e & 0xffff;
                float d = exact_d_s(A32 + row * ASTRIDE, weight + (size_t)k * DDIM,
                                    SX[row], SWN[k]);
                u64 key = ((u64)__float_as_uint(d) << 16) | (u64)k;
                atomicMin(&KEY[row], key);
            }
        }
        __syncthreads();

        // ---- epilogue: x from A32 (float4), codeword via float4 gather ----
        {
            int bidx;
            if (SOVF[erow]) {   // overflow fallback (never expected)
                float best = 3.4e38f; bidx = 0;
                for (int k = 0; k < KCODES; k++) {
                    float d = exact_d_s(A32 + erow * ASTRIDE, weight + (size_t)k * DDIM,
                                        SX[erow], SWN[k]);
                    if (d < best) { best = d; bidx = k; }
                }
            } else {
                bidx = (int)(KEY[erow] & 0xffffull);
            }

            const float4* q4 = (const float4*)(weight + (size_t)bidx * DDIM + ec0);
            const float4* a4 = (const float4*)(A32 + erow * ASTRIDE + ec0);
            float* outp = out + (size_t)b * DDIM * HWSZ + hw0 + erow;
            #pragma unroll
            for (int i4 = 0; i4 < 4; i4++) {
                float4 qv = q4[i4];
                float4 xv = a4[i4];
                const float qvv[4] = {qv.x, qv.y, qv.z, qv.w};
                const float xvv[4] = {xv.x, xv.y, xv.z, xv.w};
                #pragma unroll
                for (int j = 0; j < 4; j++) {
                    int i = i4 * 4 + j;
                    float e = __fsub_rn(qvv[j], xvv[j]);
                    outp[(size_t)(ec0 + i) * HWSZ] = __fadd_rn(xvv[j], e);
                    lloss_acc = fmaf(e, e, lloss_acc);
                }
            }
        }
        __syncthreads();   // A32/KEY/QCNT reuse safe for next tile
    }

    // ---- per-CTA loss reduction, then last CTA finishes ----
    {
        float* red = (float*)(smem + OFF_A);
        red[tid] = lloss_acc;
        __syncthreads();
        #pragma unroll
        for (int st = NTHREADS / 2; st > 0; st >>= 1) {
            if (tid < st) red[tid] += red[tid + st];
            __syncthreads();
        }
        __shared__ u32 s_last;
        if (tid == 0) {
            g_partials[blockIdx.x] = red[0];
            __threadfence();
            s_last = (atomicAdd(&g_done, 1u) == GRIDN - 1u) ? 1u : 0u;
        }
        __syncthreads();
        if (s_last && tid == 0) {
            float s = 0.f;
            for (int i = 0; i < GRIDN; i++) s += __ldcg(&g_partials[i]);
            float loss = s * 1.25f / (float)((long long)NTOT * DDIM);
            for (long long i = (long long)NTOT * DDIM; i < out_size; i++)
                out[i] = loss;
            atomicExch(&g_done, 0u);   // reset for next graph replay
        }
    }
}

extern "C" void kernel_launch(void* const* d_in, const int* in_sizes, int n_in,
                              void* d_out, int out_size)
{
    const float* input  = (const float*)d_in[0];
    const float* weight = (const float*)d_in[1];
    float* out = (float*)d_out;

    cudaFuncSetAttribute(vq_mma_kernel, cudaFuncAttributeMaxDynamicSharedMemorySize, SMEM_TOTAL);
    vq_mma_kernel<<<GRIDN, NTHREADS, SMEM_TOTAL>>>(input, weight, out, out_size);
}